// round 8
// baseline (speedup 1.0000x reference)
#include <cuda_runtime.h>

typedef unsigned long long ull;

#define NTHR   256
#define TLEN   168
#define SEQ    169
#define NB     32
#define GRID   128
#define NSTEPS 24

__device__ float g_r1[(size_t)GRID * TLEN * 64 * 32];

static __device__ __forceinline__ void ffma2(ull& d, ull a, ull b) {
    asm("fma.rn.f32x2 %0, %1, %2, %0;" : "+l"(d) : "l"(a), "l"(b));
}
static __device__ __forceinline__ ull fadd2(ull a, ull b) {
    ull r; asm("add.rn.f32x2 %0, %1, %2;" : "=l"(r) : "l"(a), "l"(b)); return r;
}
static __device__ __forceinline__ ull splat(float w) {
    ull r; asm("mov.b64 %0, {%1, %1};" : "=l"(r) : "f"(w)); return r;
}
static __device__ __forceinline__ float2 unpk(ull v) {
    float2 r; asm("mov.b64 {%0, %1}, %2;" : "=f"(r.x), "=f"(r.y) : "l"(v)); return r;
}
static __device__ __forceinline__ ull pk(float a, float b) {
    ull r; asm("mov.b64 %0, {%1, %2};" : "=l"(r) : "f"(a), "f"(b)); return r;
}
static __device__ __forceinline__ float rcp_fast(float x) {
    float r; asm("rcp.approx.f32 %0, %1;" : "=f"(r) : "f"(x)); return r;
}
static __device__ __forceinline__ float sig_fast(float x) { return rcp_fast(1.0f + __expf(-x)); }
static __device__ __forceinline__ float tanh_fast(float x) { return fmaf(2.0f, sig_fast(2.0f * x), -1.0f); }

// Wt rows gate-interleaved: slot = unit*4 + gate. Thread keeps unit u=2rg+ks, batch octet bg.
template<int K2>
static __device__ __forceinline__ void matvec_fused(const float* __restrict__ Wt,
                                                    const float* __restrict__ hhr,
                                                    int rg, int bg, int ks,
                                                    ull gI[4], ull gF[4], ull gG[4], ull gO[4])
{
    ull acc[8][4];
    #pragma unroll
    for (int r = 0; r < 8; r++)
        #pragma unroll
        for (int c = 0; c < 4; c++) acc[r][c] = 0ull;
    const float4*     wp = (const float4*)Wt + rg * 2 + ks * (K2 * 64);
    const ulonglong2* hp = (const ulonglong2*)hhr + bg * 2 + ks * (K2 * 4);

    #pragma unroll 4
    for (int k = 0; k < K2; k++) {
        float4     wA = wp[k * 64];
        float4     wB = wp[k * 64 + 1];
        ulonglong2 hA = hp[k * 4];
        ulonglong2 hB = hp[k * 4 + 1];
        ull s0 = splat(wA.x), s1 = splat(wA.y), s2 = splat(wA.z), s3 = splat(wA.w);
        ull s4 = splat(wB.x), s5 = splat(wB.y), s6 = splat(wB.z), s7 = splat(wB.w);
        ffma2(acc[0][0], s0, hA.x); ffma2(acc[0][1], s0, hA.y); ffma2(acc[0][2], s0, hB.x); ffma2(acc[0][3], s0, hB.y);
        ffma2(acc[1][0], s1, hA.x); ffma2(acc[1][1], s1, hA.y); ffma2(acc[1][2], s1, hB.x); ffma2(acc[1][3], s1, hB.y);
        ffma2(acc[2][0], s2, hA.x); ffma2(acc[2][1], s2, hA.y); ffma2(acc[2][2], s2, hB.x); ffma2(acc[2][3], s2, hB.y);
        ffma2(acc[3][0], s3, hA.x); ffma2(acc[3][1], s3, hA.y); ffma2(acc[3][2], s3, hB.x); ffma2(acc[3][3], s3, hB.y);
        ffma2(acc[4][0], s4, hA.x); ffma2(acc[4][1], s4, hA.y); ffma2(acc[4][2], s4, hB.x); ffma2(acc[4][3], s4, hB.y);
        ffma2(acc[5][0], s5, hA.x); ffma2(acc[5][1], s5, hA.y); ffma2(acc[5][2], s5, hB.x); ffma2(acc[5][3], s5, hB.y);
        ffma2(acc[6][0], s6, hA.x); ffma2(acc[6][1], s6, hA.y); ffma2(acc[6][2], s6, hB.x); ffma2(acc[6][3], s6, hB.y);
        ffma2(acc[7][0], s7, hA.x); ffma2(acc[7][1], s7, hA.y); ffma2(acc[7][2], s7, hB.x); ffma2(acc[7][3], s7, hB.y);
    }
    #pragma unroll
    for (int r = 0; r < 8; r++)
        #pragma unroll
        for (int c = 0; c < 4; c++)
            acc[r][c] = fadd2(acc[r][c], __shfl_xor_sync(0xffffffffu, acc[r][c], 16));
    #pragma unroll
    for (int j = 0; j < 4; j++) {
        gI[j] = ks ? acc[4][j] : acc[0][j];
        gF[j] = ks ? acc[5][j] : acc[1][j];
        gG[j] = ks ? acc[6][j] : acc[2][j];
        gO[j] = ks ? acc[7][j] : acc[3][j];
    }
}

static __device__ __forceinline__ void act_core(const ull gI[4], const ull gF[4],
                                                const ull gG[4], const ull gO[4],
                                                ull c[4], ull hp_[4], ull rp_[4])
{
    #pragma unroll
    for (int j = 0; j < 4; j++) {
        float2 I = unpk(gI[j]), F = unpk(gF[j]), G = unpk(gG[j]), O = unpk(gO[j]), C = unpk(c[j]);
        float c0 = fmaf(sig_fast(F.x), C.x, sig_fast(I.x) * tanh_fast(G.x));
        float c1 = fmaf(sig_fast(F.y), C.y, sig_fast(I.y) * tanh_fast(G.y));
        c[j] = pk(c0, c1);
        float h0 = sig_fast(O.x) * tanh_fast(c0);
        float h1 = sig_fast(O.y) * tanh_fast(c1);
        hp_[j] = pk(h0, h1);
        rp_[j] = pk(fmaxf(h0, 0.0f), fmaxf(h1, 0.0f));
    }
}

__global__ void __launch_bounds__(NTHR, 1)
lstm_rec_kernel(const float* __restrict__ x,
                const float* __restrict__ Wih1, const float* __restrict__ Whh1,
                const float* __restrict__ bih1, const float* __restrict__ bhh1,
                const float* __restrict__ Wih2, const float* __restrict__ Whh2,
                const float* __restrict__ bih2, const float* __restrict__ bhh2,
                const float* __restrict__ fc1w, const float* __restrict__ fc1b,
                const float* __restrict__ fc2w, const float* __restrict__ fc2b,
                float* __restrict__ out)
{
    extern __shared__ float sm[];
    float* Wt    = sm;            // [128][256] gate-interleaved   32768
    float* hh    = Wt + 32768;    // 2 x [128][16]                  4096
    float* win   = hh + 4096;     // [192][32] t-major              6144
    float* wcomb = win + 6144;    // 65
    float* bcs   = wcomb + 65;    // 1
    float* dsh   = bcs + 1;       // 32

    const int tid   = threadIdx.x;
    const int b0    = blockIdx.x * NB;
    const int group = tid >> 7;
    const int gtid  = tid & 127;
    const int warp  = gtid >> 5;
    const int lane  = gtid & 31;
    const int ks    = lane >> 4;
    const int bg    = lane & 1;
    const int rg    = (warp << 3) | ((lane >> 1) & 7);
    const int u     = 2 * rg + ks;

    float* hhg = hh + group * 2048;
    const size_t r1_base = (size_t)blockIdx.x * TLEN * 2048 + (size_t)(group * 16 + bg * 8);
    #define R1_PTR(t_) (g_r1 + r1_base + ((size_t)(t_) * 64 + u) * 32)

    for (int i = tid; i < TLEN * 32; i += NTHR) {
        int t = i >> 5, b = i & 31;
        win[t * 32 + b] = x[(size_t)(b0 + b) * SEQ + t];
    }
    if (tid < NB) dsh[tid] = x[(size_t)(b0 + tid) * SEQ + TLEN];
    if (tid < 65) {
        float s = 0.0f;
        for (int j = 0; j < 64; j++) s = fmaf(fc2w[j], fc1w[j * 65 + tid], s);
        wcomb[tid] = s;
    }
    if (tid == 65) {
        float s = fc2b[0];
        for (int j = 0; j < 64; j++) s = fmaf(fc2w[j], fc1b[j], s);
        *bcs = s;
    }
    ull wi1p[4], b1p[4], b2p[4];
    #pragma unroll
    for (int g = 0; g < 4; g++) {
        wi1p[g] = splat(Wih1[g * 64 + u]);
        b1p[g]  = splat(bih1[g * 64 + u] + bhh1[g * 64 + u]);
        b2p[g]  = splat(bih2[g * 64 + u] + bhh2[g * 64 + u]);
    }

    ull cst[4], r1n[4], gI[4], gF[4], gG[4], gO[4], hpr[4], rpr[4];

    for (int step = 0; step < NSTEPS; step++) {
        {   // stage W1 gate-interleaved
            int s = (tid & 63) * 4 + (tid >> 6);
            const float4* src = (const float4*)(Whh1 + tid * 64);
            #pragma unroll
            for (int q = 0; q < 16; q++) {
                float4 v = src[q];
                Wt[(4*q  ) * 256 + s] = v.x;
                Wt[(4*q+1) * 256 + s] = v.y;
                Wt[(4*q+2) * 256 + s] = v.z;
                Wt[(4*q+3) * 256 + s] = v.w;
            }
        }
        {
            ulonglong2 z = make_ulonglong2(0ull, 0ull);
            ((ulonglong2*)(hhg + u * 16))[bg * 2]     = z;
            ((ulonglong2*)(hhg + u * 16))[bg * 2 + 1] = z;
        }
        #pragma unroll
        for (int j = 0; j < 4; j++) cst[j] = 0ull;
        __syncthreads();

        // ===== layer 1: anti-phase matvec/act =====
        for (int p = 0; p < 2 * TLEN + 1; p++) {
            if (((p ^ group) & 1) == 0) {
                int t = (p - group) >> 1;
                if (t < TLEN)
                    matvec_fused<32>(Wt, hhg, rg, bg, ks, gI, gF, gG, gO);
            } else {
                int t = (p - 1 - group) >> 1;
                if (t >= 0) {
                    const ulonglong2* xw = (const ulonglong2*)(win + (step + t) * 32 + group * 16) + bg * 2;
                    ulonglong2 xa = xw[0], xb = xw[1];
                    ull xt[4] = {xa.x, xa.y, xb.x, xb.y};
                    #pragma unroll
                    for (int j = 0; j < 4; j++) {
                        ull tI = b1p[0]; ffma2(tI, xt[j], wi1p[0]); gI[j] = fadd2(gI[j], tI);
                        ull tF = b1p[1]; ffma2(tF, xt[j], wi1p[1]); gF[j] = fadd2(gF[j], tF);
                        ull tG = b1p[2]; ffma2(tG, xt[j], wi1p[2]); gG[j] = fadd2(gG[j], tG);
                        ull tO = b1p[3]; ffma2(tO, xt[j], wi1p[3]); gO[j] = fadd2(gO[j], tO);
                    }
                    act_core(gI, gF, gG, gO, cst, hpr, rpr);
                    ((ulonglong2*)(hhg + u * 16))[bg * 2]     = make_ulonglong2(hpr[0], hpr[1]);
                    ((ulonglong2*)(hhg + u * 16))[bg * 2 + 1] = make_ulonglong2(hpr[2], hpr[3]);
                    float* rp = R1_PTR(t);
                    ((ulonglong2*)rp)[0] = make_ulonglong2(rpr[0], rpr[1]);
                    ((ulonglong2*)rp)[1] = make_ulonglong2(rpr[2], rpr[3]);
                }
            }
            __syncthreads();
        }

        // ---- transition + stage W2 ----
        {
            int s = (tid & 63) * 4 + (tid >> 6);
            const float4* s1 = (const float4*)(Wih2 + tid * 64);
            const float4* s2 = (const float4*)(Whh2 + tid * 64);
            #pragma unroll
            for (int q = 0; q < 16; q++) {
                float4 v = s1[q];
                Wt[(4*q  ) * 256 + s] = v.x;
                Wt[(4*q+1) * 256 + s] = v.y;
                Wt[(4*q+2) * 256 + s] = v.z;
                Wt[(4*q+3) * 256 + s] = v.w;
                float4 w = s2[q];
                Wt[(64+4*q  ) * 256 + s] = w.x;
                Wt[(64+4*q+1) * 256 + s] = w.y;
                Wt[(64+4*q+2) * 256 + s] = w.z;
                Wt[(64+4*q+3) * 256 + s] = w.w;
            }
        }
        {
            ((ulonglong2*)(hhg + (64 + u) * 16))[bg * 2]     = make_ulonglong2(hpr[0], hpr[1]);  // h2_0 = h1_T
            ((ulonglong2*)(hhg + (64 + u) * 16))[bg * 2 + 1] = make_ulonglong2(hpr[2], hpr[3]);
            const ulonglong2* r0 = (const ulonglong2*)R1_PTR(0);
            ulonglong2 a = r0[0], b = r0[1];
            ((ulonglong2*)(hhg + u * 16))[bg * 2]     = a;
            ((ulonglong2*)(hhg + u * 16))[bg * 2 + 1] = b;
            const ulonglong2* r1 = (const ulonglong2*)R1_PTR(1);
            ulonglong2 c2 = r1[0], d2 = r1[1];
            r1n[0] = c2.x; r1n[1] = c2.y; r1n[2] = d2.x; r1n[3] = d2.y;
        }
        __syncthreads();

        // ===== layer 2: anti-phase matvec/act =====
        for (int p = 0; p < 2 * TLEN + 1; p++) {
            if (((p ^ group) & 1) == 0) {
                int t = (p - group) >> 1;
                if (t < TLEN)
                    matvec_fused<64>(Wt, hhg, rg, bg, ks, gI, gF, gG, gO);
            } else {
                int t = (p - 1 - group) >> 1;
                if (t >= 0) {
                    #pragma unroll
                    for (int j = 0; j < 4; j++) {
                        gI[j] = fadd2(gI[j], b2p[0]);
                        gF[j] = fadd2(gF[j], b2p[1]);
                        gG[j] = fadd2(gG[j], b2p[2]);
                        gO[j] = fadd2(gO[j], b2p[3]);
                    }
                    act_core(gI, gF, gG, gO, cst, hpr, rpr);
                    ((ulonglong2*)(hhg + (64 + u) * 16))[bg * 2]     = make_ulonglong2(hpr[0], hpr[1]);
                    ((ulonglong2*)(hhg + (64 + u) * 16))[bg * 2 + 1] = make_ulonglong2(hpr[2], hpr[3]);
                    ((ulonglong2*)(hhg + u * 16))[bg * 2]     = make_ulonglong2(r1n[0], r1n[1]);
                    ((ulonglong2*)(hhg + u * 16))[bg * 2 + 1] = make_ulonglong2(r1n[2], r1n[3]);
                    if (t + 2 < TLEN) {
                        const ulonglong2* rn = (const ulonglong2*)R1_PTR(t + 2);
                        ulonglong2 a = rn[0], b = rn[1];
                        r1n[0] = a.x; r1n[1] = a.y; r1n[2] = b.x; r1n[3] = b.y;
                    }
                }
            }
            __syncthreads();
        }

        // ===== FC (collapsed) + window append =====
        if (tid < NB) {
            const float* h2 = hh + (tid >> 4) * 2048 + (tid & 15);
            float s = *bcs + wcomb[64] * dsh[tid];
            #pragma unroll
            for (int uu = 0; uu < 64; uu++)
                s = fmaf(wcomb[uu], fmaxf(h2[(64 + uu) * 16], 0.0f), s);
            out[(size_t)(b0 + tid) * NSTEPS + step] = s;
            win[(TLEN + step) * 32 + tid] = s;
        }
        __syncthreads();
    }
    #undef R1_PTR
}

extern "C" void kernel_launch(void* const* d_in, const int* in_sizes, int n_in,
                              void* d_out, int out_size) {
    (void)in_sizes; (void)n_in; (void)out_size;
    const float* x    = (const float*)d_in[0];
    const float* Wih1 = (const float*)d_in[1];
    const float* Whh1 = (const float*)d_in[2];
    const float* bih1 = (const float*)d_in[3];
    const float* bhh1 = (const float*)d_in[4];
    const float* Wih2 = (const float*)d_in[5];
    const float* Whh2 = (const float*)d_in[6];
    const float* bih2 = (const float*)d_in[7];
    const float* bhh2 = (const float*)d_in[8];
    const float* fc1w = (const float*)d_in[9];
    const float* fc1b = (const float*)d_in[10];
    const float* fc2w = (const float*)d_in[11];
    const float* fc2b = (const float*)d_in[12];
    float* out = (float*)d_out;

    size_t smem = (size_t)(32768 + 4096 + 6144 + 65 + 1 + NB) * sizeof(float);
    cudaFuncSetAttribute(lstm_rec_kernel, cudaFuncAttributeMaxDynamicSharedMemorySize, (int)smem);
    lstm_rec_kernel<<<GRID, NTHR, smem>>>(x, Wih1, Whh1, bih1, bhh1,
                                          Wih2, Whh2, bih2, bhh2,
                                          fc1w, fc1b, fc2w, fc2b, out);
}

// round 9
// speedup vs baseline: 1.1039x; 1.1039x over previous
#include <cuda_runtime.h>
typedef unsigned long long ull;

#define NTHR   512
#define TLEN   168
#define SEQ    169
#define GRID   128
#define NSTEPS 24
#define WP     260          // Wt row pitch (floats)
#define HP     20           // hh row pitch (floats)
#define HBUF   (128*HP)     // one h buffer

__device__ float g_r1[(size_t)GRID * TLEN * 64 * 32];

static __device__ __forceinline__ void ffma2(ull& d, ull a, ull b) {
    asm("fma.rn.f32x2 %0, %1, %2, %0;" : "+l"(d) : "l"(a), "l"(b));
}
static __device__ __forceinline__ ull fadd2(ull a, ull b) {
    ull r; asm("add.rn.f32x2 %0, %1, %2;" : "=l"(r) : "l"(a), "l"(b)); return r;
}
static __device__ __forceinline__ ull splat(float w) {
    ull r; asm("mov.b64 %0, {%1, %1};" : "=l"(r) : "f"(w)); return r;
}
static __device__ __forceinline__ float2 unpk(ull v) {
    float2 r; asm("mov.b64 {%0, %1}, %2;" : "=f"(r.x), "=f"(r.y) : "l"(v)); return r;
}
static __device__ __forceinline__ ull pk(float a, float b) {
    ull r; asm("mov.b64 %0, {%1, %2};" : "=l"(r) : "f"(a), "f"(b)); return r;
}
static __device__ __forceinline__ float rcpf(float x) {
    float r; asm("rcp.approx.f32 %0, %1;" : "=f"(r) : "f"(x)); return r;
}
static __device__ __forceinline__ float sigf(float x) { return rcpf(1.0f + __expf(-x)); }
static __device__ __forceinline__ float tanhf_(float x) { return fmaf(2.0f, sigf(2.0f * x), -1.0f); }

#define GBAR(id) asm volatile("bar.sync %0, %1;" :: "r"(id), "r"(256) : "memory")

// 8 rows x 8 batches, k = 4*kk + kq interleaved. Ends with own unit's 4 gates x 4 batches in regs.
template<int K4>
static __device__ __forceinline__ void matvec(const float* __restrict__ Wt,
                                              const float* __restrict__ hb,
                                              int rg8, int bo, int b0, int b1,
                                              ull gI[2], ull gF[2], ull gG[2], ull gO[2])
{
    ull acc[8][4];
    #pragma unroll
    for (int r = 0; r < 8; r++)
        #pragma unroll
        for (int c = 0; c < 4; c++) acc[r][c] = 0ull;
    const int kq = b1 * 2 + b0;
    const float4*     wp = (const float4*)(Wt + kq * WP) + rg8 * 2;
    const ulonglong2* hp = (const ulonglong2*)(hb + kq * HP + bo * 8);

    #pragma unroll 4
    for (int kk = 0; kk < K4; kk++) {
        float4     wA = wp[kk * WP];
        float4     wB = wp[kk * WP + 1];
        ulonglong2 hA = hp[kk * HP];
        ulonglong2 hB = hp[kk * HP + 1];
        ull s0 = splat(wA.x), s1 = splat(wA.y), s2 = splat(wA.z), s3 = splat(wA.w);
        ull s4 = splat(wB.x), s5 = splat(wB.y), s6 = splat(wB.z), s7 = splat(wB.w);
        ffma2(acc[0][0],s0,hA.x); ffma2(acc[0][1],s0,hA.y); ffma2(acc[0][2],s0,hB.x); ffma2(acc[0][3],s0,hB.y);
        ffma2(acc[1][0],s1,hA.x); ffma2(acc[1][1],s1,hA.y); ffma2(acc[1][2],s1,hB.x); ffma2(acc[1][3],s1,hB.y);
        ffma2(acc[2][0],s2,hA.x); ffma2(acc[2][1],s2,hA.y); ffma2(acc[2][2],s2,hB.x); ffma2(acc[2][3],s2,hB.y);
        ffma2(acc[3][0],s3,hA.x); ffma2(acc[3][1],s3,hA.y); ffma2(acc[3][2],s3,hB.x); ffma2(acc[3][3],s3,hB.y);
        ffma2(acc[4][0],s4,hA.x); ffma2(acc[4][1],s4,hA.y); ffma2(acc[4][2],s4,hB.x); ffma2(acc[4][3],s4,hB.y);
        ffma2(acc[5][0],s5,hA.x); ffma2(acc[5][1],s5,hA.y); ffma2(acc[5][2],s5,hB.x); ffma2(acc[5][3],s5,hB.y);
        ffma2(acc[6][0],s6,hA.x); ffma2(acc[6][1],s6,hA.y); ffma2(acc[6][2],s6,hB.x); ffma2(acc[6][3],s6,hB.y);
        ffma2(acc[7][0],s7,hA.x); ffma2(acc[7][1],s7,hA.y); ffma2(acc[7][2],s7,hB.x); ffma2(acc[7][3],s7,hB.y);
    }
    ull red1[4][4];
    #pragma unroll
    for (int r = 0; r < 4; r++)
        #pragma unroll
        for (int c = 0; c < 4; c++) {
            ull keep = b0 ? acc[4+r][c] : acc[r][c];
            ull send = b0 ? acc[r][c]   : acc[4+r][c];
            red1[r][c] = fadd2(keep, __shfl_xor_sync(0xffffffffu, send, 8));
        }
    ull red2[2][4];
    #pragma unroll
    for (int r = 0; r < 2; r++)
        #pragma unroll
        for (int c = 0; c < 4; c++) {
            ull keep = b1 ? red1[2+r][c] : red1[r][c];
            ull send = b1 ? red1[r][c]   : red1[2+r][c];
            red2[r][c] = fadd2(keep, __shfl_xor_sync(0xffffffffu, send, 16));
        }
    ull recv[4];
    #pragma unroll
    for (int j = 0; j < 4; j++) {
        ull send = b1 ? red2[j>>1][j&1] : red2[j>>1][2+(j&1)];
        recv[j] = __shfl_xor_sync(0xffffffffu, send, 16);
    }
    #pragma unroll
    for (int i = 0; i < 2; i++) {
        gI[i] = b1 ? recv[i]      : red2[0][i];
        gF[i] = b1 ? recv[2+i]    : red2[1][i];
        gG[i] = b1 ? red2[0][2+i] : recv[i];
        gO[i] = b1 ? red2[1][2+i] : recv[2+i];
    }
}

static __device__ __forceinline__ void act2(const ull gI[2], const ull gF[2],
                                            const ull gG[2], const ull gO[2],
                                            ull c[2], ull h[2], ull rl[2])
{
    #pragma unroll
    for (int j = 0; j < 2; j++) {
        float2 I = unpk(gI[j]), F = unpk(gF[j]), G = unpk(gG[j]), O = unpk(gO[j]), C = unpk(c[j]);
        float c0 = fmaf(sigf(F.x), C.x, sigf(I.x) * tanhf_(G.x));
        float c1 = fmaf(sigf(F.y), C.y, sigf(I.y) * tanhf_(G.y));
        c[j] = pk(c0, c1);
        float h0 = sigf(O.x) * tanhf_(c0);
        float h1 = sigf(O.y) * tanhf_(c1);
        h[j]  = pk(h0, h1);
        rl[j] = pk(fmaxf(h0, 0.0f), fmaxf(h1, 0.0f));
    }
}

__global__ void __launch_bounds__(NTHR, 1)
lstm_rec_kernel(const float* __restrict__ x,
                const float* __restrict__ Wih1, const float* __restrict__ Whh1,
                const float* __restrict__ bih1, const float* __restrict__ bhh1,
                const float* __restrict__ Wih2, const float* __restrict__ Whh2,
                const float* __restrict__ bih2, const float* __restrict__ bhh2,
                const float* __restrict__ fc1w, const float* __restrict__ fc1b,
                const float* __restrict__ fc2w, const float* __restrict__ fc2b,
                float* __restrict__ out)
{
    extern __shared__ float sm[];
    float* Wt    = sm;                  // [128][WP]        33280
    float* hh    = Wt + 128 * WP;       // 2 grp x 2 buf x [128][HP] = 10240
    float* win   = hh + 4 * HBUF;       // [192][32]         6144
    float* wcomb = win + 6144;          // 65
    float* bcs   = wcomb + 65;          // 1
    float* dsh   = bcs + 1;             // 32

    const int tid  = threadIdx.x;
    const int b0g  = blockIdx.x * 32;
    const int grp  = tid >> 8;
    const int lane = tid & 31;
    const int gw   = (tid >> 5) & 7;
    const int tile = gw * 8 + (lane & 7);
    const int rg8  = tile >> 1;
    const int bo   = tile & 1;
    const int b0   = (lane >> 3) & 1;
    const int b1   = lane >> 4;
    const int u    = rg8 * 2 + b0;           // this thread's unit
    const int bq   = bo * 8 + b1 * 4;        // batch quad within group
    float* hhG = hh + grp * 2 * HBUF;
    #define R1(t_) (g_r1 + (((size_t)blockIdx.x * TLEN + (t_)) * 64 + u) * 32 + grp * 16 + bq)

    for (int i = tid; i < TLEN * 32; i += NTHR) {
        int t = i >> 5, b = i & 31;
        win[t * 32 + b] = x[(size_t)(b0g + b) * SEQ + t];
    }
    if (tid < 32) dsh[tid] = x[(size_t)(b0g + tid) * SEQ + TLEN];
    if (tid < 65) {
        float s = 0.0f;
        for (int j = 0; j < 64; j++) s = fmaf(fc2w[j], fc1w[j * 65 + tid], s);
        wcomb[tid] = s;
    }
    if (tid == 65) {
        float s = fc2b[0];
        for (int j = 0; j < 64; j++) s = fmaf(fc2w[j], fc1b[j], s);
        *bcs = s;
    }
    float wi1f[4], b1f[4], b2f[4];
    #pragma unroll
    for (int g = 0; g < 4; g++) {
        wi1f[g] = Wih1[g * 64 + u];
        b1f[g]  = bih1[g * 64 + u] + bhh1[g * 64 + u];
        b2f[g]  = bih2[g * 64 + u] + bhh2[g * 64 + u];
    }

    ull cst[2], r1n[2], gI[2], gF[2], gG[2], gO[2], hpr[2], rpr[2];

    for (int step = 0; step < NSTEPS; step++) {
        {   // stage W1: Wt[k][slot], slot = (row&63)*4 + row>>6
            int r = tid >> 1, hf = tid & 1;
            int s = (r & 63) * 4 + (r >> 6);
            const float4* src = (const float4*)(Whh1 + r * 64) + hf * 8;
            #pragma unroll
            for (int q = 0; q < 8; q++) {
                float4 v = src[q];
                int k = hf * 32 + q * 4;
                Wt[(k  ) * WP + s] = v.x;
                Wt[(k+1) * WP + s] = v.y;
                Wt[(k+2) * WP + s] = v.z;
                Wt[(k+3) * WP + s] = v.w;
            }
        }
        *(ulonglong2*)(hhG + u * HP + bq) = make_ulonglong2(0ull, 0ull);  // h1(0)=0 in buf0
        cst[0] = cst[1] = 0ull;
        __syncthreads();

        // ===== layer 1 =====
        for (int t = 0; t < TLEN; t++) {
            matvec<16>(Wt, hhG + (t & 1) * HBUF, rg8, bo, b0, b1, gI, gF, gG, gO);
            ulonglong2 xv = *(const ulonglong2*)(win + (step + t) * 32 + grp * 16 + bq);
            ull xt[2] = {xv.x, xv.y};
            #pragma unroll
            for (int i = 0; i < 2; i++) {
                ull tI = splat(b1f[0]); ffma2(tI, xt[i], splat(wi1f[0])); gI[i] = fadd2(gI[i], tI);
                ull tF = splat(b1f[1]); ffma2(tF, xt[i], splat(wi1f[1])); gF[i] = fadd2(gF[i], tF);
                ull tG = splat(b1f[2]); ffma2(tG, xt[i], splat(wi1f[2])); gG[i] = fadd2(gG[i], tG);
                ull tO = splat(b1f[3]); ffma2(tO, xt[i], splat(wi1f[3])); gO[i] = fadd2(gO[i], tO);
            }
            act2(gI, gF, gG, gO, cst, hpr, rpr);
            *(ulonglong2*)(hhG + ((t + 1) & 1) * HBUF + u * HP + bq) = make_ulonglong2(hpr[0], hpr[1]);
            *(ulonglong2*)R1(t) = make_ulonglong2(rpr[0], rpr[1]);
            GBAR(1 + grp);
        }

        __syncthreads();
        {   // stage W2: k 0..63 = Wih2, 64..127 = Whh2
            int r2 = tid & 255;
            const float* W = (tid < 256) ? Wih2 : Whh2;
            int kb = (tid < 256) ? 0 : 64;
            int s = (r2 & 63) * 4 + (r2 >> 6);
            const float4* s4 = (const float4*)(W + r2 * 64);
            #pragma unroll
            for (int q = 0; q < 16; q++) {
                float4 v = s4[q];
                int k = kb + q * 4;
                Wt[(k  ) * WP + s] = v.x;
                Wt[(k+1) * WP + s] = v.y;
                Wt[(k+2) * WP + s] = v.z;
                Wt[(k+3) * WP + s] = v.w;
            }
        }
        {   // transition into buf0: rows 64+u = h1_T (regs), rows u = r1(0); prefetch r1(1)
            *(ulonglong2*)(hhG + (64 + u) * HP + bq) = make_ulonglong2(hpr[0], hpr[1]);
            ulonglong2 rz = *(const ulonglong2*)R1(0);
            *(ulonglong2*)(hhG + u * HP + bq) = rz;
            ulonglong2 rn = *(const ulonglong2*)R1(1);
            r1n[0] = rn.x; r1n[1] = rn.y;
        }
        __syncthreads();

        // ===== layer 2 =====
        for (int t = 0; t < TLEN; t++) {
            matvec<32>(Wt, hhG + (t & 1) * HBUF, rg8, bo, b0, b1, gI, gF, gG, gO);
            #pragma unroll
            for (int i = 0; i < 2; i++) {
                gI[i] = fadd2(gI[i], splat(b2f[0]));
                gF[i] = fadd2(gF[i], splat(b2f[1]));
                gG[i] = fadd2(gG[i], splat(b2f[2]));
                gO[i] = fadd2(gO[i], splat(b2f[3]));
            }
            act2(gI, gF, gG, gO, cst, hpr, rpr);
            float* bw = hhG + ((t + 1) & 1) * HBUF;
            *(ulonglong2*)(bw + (64 + u) * HP + bq) = make_ulonglong2(hpr[0], hpr[1]);
            *(ulonglong2*)(bw + u * HP + bq)        = make_ulonglong2(r1n[0], r1n[1]);
            if (t + 2 < TLEN) {
                ulonglong2 rn = *(const ulonglong2*)R1(t + 2);
                r1n[0] = rn.x; r1n[1] = rn.y;
            }
            GBAR(1 + grp);
        }
        __syncthreads();

        // ===== FC (collapsed) + window append =====
        if (tid < 32) {
            const float* h2 = hh + (tid >> 4) * 2 * HBUF + (tid & 15);  // buf0
            float s = *bcs + wcomb[64] * dsh[tid];
            #pragma unroll
            for (int uu = 0; uu < 64; uu++)
                s = fmaf(wcomb[uu], fmaxf(h2[(64 + uu) * HP], 0.0f), s);
            out[(size_t)(b0g + tid) * NSTEPS + step] = s;
            win[(TLEN + step) * 32 + tid] = s;
        }
        __syncthreads();
    }
    #undef R1
}

extern "C" void kernel_launch(void* const* d_in, const int* in_sizes, int n_in,
                              void* d_out, int out_size) {
    (void)in_sizes; (void)n_in; (void)out_size;
    const float* x    = (const float*)d_in[0];
    const float* Wih1 = (const float*)d_in[1];
    const float* Whh1 = (const float*)d_in[2];
    const float* bih1 = (const float*)d_in[3];
    const float* bhh1 = (const float*)d_in[4];
    const float* Wih2 = (const float*)d_in[5];
    const float* Whh2 = (const float*)d_in[6];
    const float* bih2 = (const float*)d_in[7];
    const float* bhh2 = (const float*)d_in[8];
    const float* fc1w = (const float*)d_in[9];
    const float* fc1b = (const float*)d_in[10];
    const float* fc2w = (const float*)d_in[11];
    const float* fc2b = (const float*)d_in[12];
    float* out = (float*)d_out;

    size_t smem = (size_t)(128 * WP + 4 * HBUF + 6144 + 65 + 1 + 32) * sizeof(float);
    cudaFuncSetAttribute(lstm_rec_kernel, cudaFuncAttributeMaxDynamicSharedMemorySize, (int)smem);
    lstm_rec_kernel<<<GRID, NTHR, smem>>>(x, Wih1, Whh1, bih1, bhh1,
                                          Wih2, Whh2, bih2, bhh2,
                                          fc1w, fc1b, fc2w, fc2b, out);
}

// round 11
// speedup vs baseline: 2.0631x; 1.8690x over previous
#include <cuda_runtime.h>
#include <cuda_bf16.h>

typedef unsigned int u32;
typedef unsigned short u16;
typedef unsigned long long u64;

#define GRID   128
#define NTHR   512
#define TLEN   168
#define SEQ    169
#define NSTEPS 24
#define HP     68            // H row pitch (u32)
#define HBUF   (32*HP)       // u32 per H buffer

// r1 staging: packed (hi16<<16)|lo16 per value, [GRID][TLEN][64 units][32 batches]
__device__ u32 g_r1[(size_t)GRID * TLEN * 64 * 32];

static __device__ __forceinline__ float rcpf(float x){float r;asm("rcp.approx.f32 %0,%1;":"=f"(r):"f"(x));return r;}
static __device__ __forceinline__ float sigf(float x){return rcpf(1.0f+__expf(-x));}
static __device__ __forceinline__ float tanhf_(float x){return fmaf(2.0f,sigf(2.0f*x),-1.0f);}

static __device__ __forceinline__ void split1(float x,u16&hi,u16&lo){
    __nv_bfloat16 h=__float2bfloat16_rn(x);
    hi=__bfloat16_as_ushort(h);
    lo=__bfloat16_as_ushort(__float2bfloat16_rn(x-__bfloat162float(h)));
}
static __device__ __forceinline__ void splitpack(float x0,float x1,u32&hi,u32&lo){
    u16 h0,l0,h1,l1; split1(x0,h0,l0); split1(x1,h1,l1);
    hi=((u32)h1<<16)|h0; lo=((u32)l1<<16)|l0;
}
static __device__ __forceinline__ void mma4(float c[4],const u32 a[4],u32 b0,u32 b1){
    asm volatile("mma.sync.aligned.m16n8k16.row.col.f32.bf16.bf16.f32 "
        "{%0,%1,%2,%3},{%4,%5,%6,%7},{%8,%9},{%0,%1,%2,%3};"
        :"+f"(c[0]),"+f"(c[1]),"+f"(c[2]),"+f"(c[3])
        :"r"(a[0]),"r"(a[1]),"r"(a[2]),"r"(a[3]),"r"(b0),"r"(b1));
}

// 3-pass split-precision mma over KK ksteps, 4 ntiles
template<int KK>
static __device__ __forceinline__ void do_mma(const u32* __restrict__ Bh,
                                              const u32* __restrict__ Bl,
                                              const u32 Ahi[8][4], const u32 Alo[8][4],
                                              int g, int tg, float c[4][4])
{
    #pragma unroll
    for (int kk = 0; kk < KK; kk++) {
        #pragma unroll
        for (int n = 0; n < 4; n++) {
            int idx = (8*n + g)*HP + 8*kk + tg;
            u32 bh0 = Bh[idx], bh1 = Bh[idx+4];
            u32 bl0 = Bl[idx], bl1 = Bl[idx+4];
            mma4(c[n], Ahi[kk], bh0, bh1);
            mma4(c[n], Ahi[kk], bl0, bl1);
            mma4(c[n], Alo[kk], bh0, bh1);
        }
    }
}

__global__ void __launch_bounds__(NTHR, 1)
lstm_rec_kernel(const float* __restrict__ x,
                const float* __restrict__ Wih1, const float* __restrict__ Whh1,
                const float* __restrict__ bih1, const float* __restrict__ bhh1,
                const float* __restrict__ Wih2, const float* __restrict__ Whh2,
                const float* __restrict__ bih2, const float* __restrict__ bhh2,
                const float* __restrict__ fc1w, const float* __restrict__ fc1b,
                const float* __restrict__ fc2w, const float* __restrict__ fc2b,
                float* __restrict__ out)
{
    extern __shared__ u32 smu[];
    u32*   Hhi  = smu;                       // [2][32][HP]
    u32*   Hlo  = Hhi + 2*HBUF;              // [2][32][HP]
    float* win  = (float*)(Hlo + 2*HBUF);    // [192][32]
    float* scr  = win + 192*32;              // [64][32]
    float* wcomb= scr + 2048;                // [65]
    float* bcs  = wcomb + 65;
    float* dsh  = wcomb + 66;                // [32]

    const int tid  = threadIdx.x;
    const int b0g  = blockIdx.x * 32;
    const int warp = tid >> 5, lane = tid & 31;
    const int g    = lane >> 2, tg = lane & 3;
    const int q    = 4*warp + (g & 3);       // this thread's unit
    const bool glo = (g < 4);
    const int bb0  = (glo ? 0 : 16) + 2*tg;  // batches: bb0,bb0+1,bb0+8,bb0+9
    const int rowA = (g >> 2)*64 + 4*warp + (g & 3);  // W row for tile row g (rowB = rowA+128)

    // ---- one-time init ----
    for (int i = tid; i < TLEN*32; i += NTHR) {
        int t = i >> 5, b = i & 31;
        win[t*32 + b] = x[(size_t)(b0g + b)*SEQ + t];
    }
    if (tid < 32) dsh[tid] = x[(size_t)(b0g + tid)*SEQ + TLEN];
    if (tid < 65) {
        float s = 0.0f;
        for (int j = 0; j < 64; j++) s = fmaf(fc2w[j], fc1w[j*65 + tid], s);
        wcomb[tid] = s;
    }
    if (tid == 65) {
        float s = fc2b[0];
        for (int j = 0; j < 64; j++) s = fmaf(fc2w[j], fc1b[j], s);
        *bcs = s;
    }
    float wi1f[4], b1f[4], b2f[4];
    #pragma unroll
    for (int ga = 0; ga < 4; ga++) {
        wi1f[ga] = Wih1[ga*64 + q];
        b1f[ga]  = bih1[ga*64 + q] + bhh1[ga*64 + q];
        b2f[ga]  = bih2[ga*64 + q] + bhh2[ga*64 + q];
    }
    u32* r1p = g_r1 + (size_t)blockIdx.x * TLEN * 2048;

    u32 Ahi[8][4], Alo[8][4];
    float cst[4], hl[4];
    u32 r1n[4];

    for (int step = 0; step < NSTEPS; step++) {
        // ---- stage A regs from Whh1 (K=64) ----
        #pragma unroll
        for (int kk = 0; kk < 4; kk++) {
            int k1 = 16*kk + 2*tg, k2 = k1 + 8;
            float2 vA1 = *(const float2*)(Whh1 + rowA*64 + k1);
            float2 vB1 = *(const float2*)(Whh1 + (rowA+128)*64 + k1);
            float2 vA2 = *(const float2*)(Whh1 + rowA*64 + k2);
            float2 vB2 = *(const float2*)(Whh1 + (rowA+128)*64 + k2);
            splitpack(vA1.x, vA1.y, Ahi[kk][0], Alo[kk][0]);
            splitpack(vB1.x, vB1.y, Ahi[kk][1], Alo[kk][1]);
            splitpack(vA2.x, vA2.y, Ahi[kk][2], Alo[kk][2]);
            splitpack(vB2.x, vB2.y, Ahi[kk][3], Alo[kk][3]);
        }
        // zero H buf0 k<64 region (h1(0)=0)
        for (int i = tid; i < 1024; i += NTHR) {
            int b = i >> 5, w = i & 31;
            Hhi[b*HP + w] = 0u; Hlo[b*HP + w] = 0u;
        }
        cst[0] = cst[1] = cst[2] = cst[3] = 0.0f;
        __syncthreads();

        // ================= layer 1 =================
        for (int t = 0; t < TLEN; t++) {
            float c[4][4];
            #pragma unroll
            for (int n = 0; n < 4; n++) { c[n][0]=c[n][1]=c[n][2]=c[n][3]=0.0f; }
            do_mma<4>(Hhi + (t&1)*HBUF, Hlo + (t&1)*HBUF, Ahi, Alo, g, tg, c);
            float rx[2][4];
            #pragma unroll
            for (int n2 = 0; n2 < 2; n2++)
                #pragma unroll
                for (int j = 0; j < 4; j++) {
                    float send = glo ? c[2+n2][j] : c[n2][j];
                    rx[n2][j] = __shfl_xor_sync(0xffffffffu, send, 16);
                }
            float2 xv0 = *(const float2*)(win + (step+t)*32 + bb0);
            float2 xv1 = *(const float2*)(win + (step+t)*32 + bb0 + 8);
            float xa[4] = {xv0.x, xv0.y, xv1.x, xv1.y};
            u16* HhW = (u16*)(Hhi + ((t+1)&1)*HBUF);
            u16* HlW = (u16*)(Hlo + ((t+1)&1)*HBUF);
            u32 pk2[4];
            #pragma unroll
            for (int j = 0; j < 4; j++) {
                int n2 = j >> 1, col = j & 1;
                float gi = glo ? c[n2][col]     : rx[n2][col];
                float gg = glo ? c[n2][2+col]   : rx[n2][2+col];
                float f  = glo ? rx[n2][col]    : c[2+n2][col];
                float o  = glo ? rx[n2][2+col]  : c[2+n2][2+col];
                gi += fmaf(xa[j], wi1f[0], b1f[0]);
                f  += fmaf(xa[j], wi1f[1], b1f[1]);
                gg += fmaf(xa[j], wi1f[2], b1f[2]);
                o  += fmaf(xa[j], wi1f[3], b1f[3]);
                float cn = fmaf(sigf(f), cst[j], sigf(gi)*tanhf_(gg));
                cst[j] = cn;
                float h = sigf(o)*tanhf_(cn);
                hl[j] = h;
                u16 hi, lo; split1(h, hi, lo);
                int batch = bb0 + 8*n2 + col;
                HhW[batch*136 + q] = hi; HlW[batch*136 + q] = lo;
                u16 rh, rl; split1(fmaxf(h, 0.0f), rh, rl);
                pk2[j] = ((u32)rh << 16) | rl;
            }
            u32* rw = r1p + (size_t)t*2048 + q*32 + bb0;
            *(u64*)rw       = ((u64)pk2[1] << 32) | pk2[0];
            *(u64*)(rw + 8) = ((u64)pk2[3] << 32) | pk2[2];
            __syncthreads();
        }

        // ---- stage A regs for layer 2 (K=128: Wih2 | Whh2) ----
        #pragma unroll
        for (int kk = 0; kk < 8; kk++) {
            const float* W = (kk < 4) ? Wih2 : Whh2;
            int k1 = 16*(kk & 3) + 2*tg, k2 = k1 + 8;
            float2 vA1 = *(const float2*)(W + rowA*64 + k1);
            float2 vB1 = *(const float2*)(W + (rowA+128)*64 + k1);
            float2 vA2 = *(const float2*)(W + rowA*64 + k2);
            float2 vB2 = *(const float2*)(W + (rowA+128)*64 + k2);
            splitpack(vA1.x, vA1.y, Ahi[kk][0], Alo[kk][0]);
            splitpack(vB1.x, vB1.y, Ahi[kk][1], Alo[kk][1]);
            splitpack(vA2.x, vA2.y, Ahi[kk][2], Alo[kk][2]);
            splitpack(vB2.x, vB2.y, Ahi[kk][3], Alo[kk][3]);
        }
        // ---- transition: buf0 gets h1_T at k=64+q, r1(0) at k=q; prefetch r1(1) ----
        {
            u16* H0h = (u16*)Hhi; u16* H0l = (u16*)Hlo;
            u64 rz0 = *(const u64*)(r1p + q*32 + bb0);
            u64 rz1 = *(const u64*)(r1p + q*32 + bb0 + 8);
            u32 pz[4] = {(u32)rz0, (u32)(rz0 >> 32), (u32)rz1, (u32)(rz1 >> 32)};
            #pragma unroll
            for (int j = 0; j < 4; j++) {
                int batch = bb0 + 8*(j >> 1) + (j & 1);
                u16 hi, lo; split1(hl[j], hi, lo);
                H0h[batch*136 + 64 + q] = hi;  H0l[batch*136 + 64 + q] = lo;
                H0h[batch*136 + q] = (u16)(pz[j] >> 16);
                H0l[batch*136 + q] = (u16)(pz[j] & 0xffffu);
            }
            u64 rn0 = *(const u64*)(r1p + 2048 + q*32 + bb0);
            u64 rn1 = *(const u64*)(r1p + 2048 + q*32 + bb0 + 8);
            r1n[0] = (u32)rn0; r1n[1] = (u32)(rn0 >> 32);
            r1n[2] = (u32)rn1; r1n[3] = (u32)(rn1 >> 32);
        }
        __syncthreads();

        // ================= layer 2 =================
        for (int t = 0; t < TLEN; t++) {
            float c[4][4];
            #pragma unroll
            for (int n = 0; n < 4; n++) { c[n][0]=c[n][1]=c[n][2]=c[n][3]=0.0f; }
            do_mma<8>(Hhi + (t&1)*HBUF, Hlo + (t&1)*HBUF, Ahi, Alo, g, tg, c);
            float rx[2][4];
            #pragma unroll
            for (int n2 = 0; n2 < 2; n2++)
                #pragma unroll
                for (int j = 0; j < 4; j++) {
                    float send = glo ? c[2+n2][j] : c[n2][j];
                    rx[n2][j] = __shfl_xor_sync(0xffffffffu, send, 16);
                }
            u16* HhW = (u16*)(Hhi + ((t+1)&1)*HBUF);
            u16* HlW = (u16*)(Hlo + ((t+1)&1)*HBUF);
            #pragma unroll
            for (int j = 0; j < 4; j++) {
                int n2 = j >> 1, col = j & 1;
                float gi = (glo ? c[n2][col]    : rx[n2][col])    + b2f[0];
                float f  = (glo ? rx[n2][col]   : c[2+n2][col])   + b2f[1];
                float gg = (glo ? c[n2][2+col]  : rx[n2][2+col])  + b2f[2];
                float o  = (glo ? rx[n2][2+col] : c[2+n2][2+col]) + b2f[3];
                float cn = fmaf(sigf(f), cst[j], sigf(gi)*tanhf_(gg));
                cst[j] = cn;
                float h = sigf(o)*tanhf_(cn);
                int batch = bb0 + 8*n2 + col;
                if (t + 1 < TLEN) {
                    u16 hi, lo; split1(h, hi, lo);
                    HhW[batch*136 + 64 + q] = hi;  HlW[batch*136 + 64 + q] = lo;
                    HhW[batch*136 + q] = (u16)(r1n[j] >> 16);
                    HlW[batch*136 + q] = (u16)(r1n[j] & 0xffffu);
                } else {
                    scr[q*32 + batch] = fmaxf(h, 0.0f);
                }
            }
            if (t + 2 < TLEN) {
                u64 rn0 = *(const u64*)(r1p + (size_t)(t+2)*2048 + q*32 + bb0);
                u64 rn1 = *(const u64*)(r1p + (size_t)(t+2)*2048 + q*32 + bb0 + 8);
                r1n[0] = (u32)rn0; r1n[1] = (u32)(rn0 >> 32);
                r1n[2] = (u32)rn1; r1n[3] = (u32)(rn1 >> 32);
            }
            __syncthreads();
        }

        // ---- FC (collapsed) + window append ----
        if (tid < 32) {
            float s = *bcs + wcomb[64] * dsh[tid];
            #pragma unroll
            for (int uu = 0; uu < 64; uu++)
                s = fmaf(wcomb[uu], scr[uu*32 + tid], s);
            out[(size_t)(b0g + tid)*NSTEPS + step] = s;
            win[(TLEN + step)*32 + tid] = s;
        }
        __syncthreads();
    }
}

extern "C" void kernel_launch(void* const* d_in, const int* in_sizes, int n_in,
                              void* d_out, int out_size) {
    (void)in_sizes; (void)n_in; (void)out_size;
    const float* x    = (const float*)d_in[0];
    const float* Wih1 = (const float*)d_in[1];
    const float* Whh1 = (const float*)d_in[2];
    const float* bih1 = (const float*)d_in[3];
    const float* bhh1 = (const float*)d_in[4];
    const float* Wih2 = (const float*)d_in[5];
    const float* Whh2 = (const float*)d_in[6];
    const float* bih2 = (const float*)d_in[7];
    const float* bhh2 = (const float*)d_in[8];
    const float* fc1w = (const float*)d_in[9];
    const float* fc1b = (const float*)d_in[10];
    const float* fc2w = (const float*)d_in[11];
    const float* fc2b = (const float*)d_in[12];
    float* out = (float*)d_out;

    size_t smem = (size_t)(4*HBUF + 6144 + 2048 + 100) * 4;
    cudaFuncSetAttribute(lstm_rec_kernel, cudaFuncAttributeMaxDynamicSharedMemorySize, (int)smem);
    lstm_rec_kernel<<<GRID, NTHR, smem>>>(x, Wih1, Whh1, bih1, bhh1,
                                          Wih2, Whh2, bih2, bhh2,
                                          fc1w, fc1b, fc2w, fc2b, out);
}

// round 12
// speedup vs baseline: 2.1159x; 1.0256x over previous
#include <cuda_runtime.h>
#include <cuda_bf16.h>

typedef unsigned int u32;
typedef unsigned short u16;
typedef unsigned long long u64;

#define GRID   128
#define NTHR   512
#define TLEN   168
#define SEQ    169
#define NSTEPS 24
#define PB     80                 // H row pitch in bytes (20 banks -> conflict-free 8-row sets)
#define HBUFB  (256 * PB)         // one H buffer (rows 0-127 hi, 128-255 lo)

#define OFF_H    0
#define OFF_WIN  (2 * HBUFB)              // 40960
#define OFF_SCR  (OFF_WIN + 192*32*4)     // 65536
#define OFF_MISC (OFF_SCR + 64*32*4)      // 73728
#define SMEM_BYTES (OFF_MISC + 512)

// r1 staging, separate bf16 hi / lo planes: [GRID][TLEN][64 units][32 batches]
__device__ u16 g_r1h[(size_t)GRID * TLEN * 64 * 32];
__device__ u16 g_r1l[(size_t)GRID * TLEN * 64 * 32];

static __device__ __forceinline__ float rcpf(float x){float r;asm("rcp.approx.f32 %0,%1;":"=f"(r):"f"(x));return r;}
static __device__ __forceinline__ float sigf(float x){return rcpf(1.0f+__expf(-x));}
static __device__ __forceinline__ float tanhf_(float x){return fmaf(2.0f,sigf(2.0f*x),-1.0f);}

static __device__ __forceinline__ void split1(float x,u16&hi,u16&lo){
    __nv_bfloat16 h=__float2bfloat16_rn(x);
    hi=__bfloat16_as_ushort(h);
    lo=__bfloat16_as_ushort(__float2bfloat16_rn(x-__bfloat162float(h)));
}
static __device__ __forceinline__ void splitpack(float x0,float x1,u32&hi,u32&lo){
    u16 h0,l0,h1,l1; split1(x0,h0,l0); split1(x1,h1,l1);
    hi=((u32)h1<<16)|h0; lo=((u32)l1<<16)|l0;
}
static __device__ __forceinline__ void mma4(float c[4],const u32 a[4],u32 b0,u32 b1){
    asm volatile("mma.sync.aligned.m16n8k16.row.col.f32.bf16.bf16.f32 "
        "{%0,%1,%2,%3},{%4,%5,%6,%7},{%8,%9},{%0,%1,%2,%3};"
        :"+f"(c[0]),"+f"(c[1]),"+f"(c[2]),"+f"(c[3])
        :"r"(a[0]),"r"(a[1]),"r"(a[2]),"r"(a[3]),"r"(b0),"r"(b1));
}
static __device__ __forceinline__ void ldm4t(u32 addr,u32&r0,u32&r1,u32&r2,u32&r3){
    asm volatile("ldmatrix.sync.aligned.m8n8.x4.trans.shared.b16 {%0,%1,%2,%3}, [%4];"
        :"=r"(r0),"=r"(r1),"=r"(r2),"=r"(r3):"r"(addr));
}

// 3-pass split-precision GEMM over KK 16-wide ksteps. hb = smem addr of H buffer + lane offset.
template<int KK>
static __device__ __forceinline__ void do_mma(u32 hb,
                                              const u32 Ahi[8][4], const u32 Alo[8][4],
                                              float c[4][4])
{
    #pragma unroll
    for (int kk = 0; kk < KK; kk++) {
        u32 a0 = hb + (u32)(kk * 16 * PB);
        u32 bh[8], bl[8];
        ldm4t(a0,                bh[0],bh[1],bh[2],bh[3]);
        ldm4t(a0+32,             bh[4],bh[5],bh[6],bh[7]);
        ldm4t(a0+128*PB,         bl[0],bl[1],bl[2],bl[3]);
        ldm4t(a0+128*PB+32,      bl[4],bl[5],bl[6],bl[7]);
        #pragma unroll
        for (int n = 0; n < 4; n++) {
            mma4(c[n], Ahi[kk], bh[2*n], bh[2*n+1]);
            mma4(c[n], Ahi[kk], bl[2*n], bl[2*n+1]);
            mma4(c[n], Alo[kk], bh[2*n], bh[2*n+1]);
        }
    }
}

__global__ void __launch_bounds__(NTHR, 1)
lstm_rec_kernel(const float* __restrict__ x,
                const float* __restrict__ Wih1, const float* __restrict__ Whh1,
                const float* __restrict__ bih1, const float* __restrict__ bhh1,
                const float* __restrict__ Wih2, const float* __restrict__ Whh2,
                const float* __restrict__ bih2, const float* __restrict__ bhh2,
                const float* __restrict__ fc1w, const float* __restrict__ fc1b,
                const float* __restrict__ fc2w, const float* __restrict__ fc2b,
                float* __restrict__ out)
{
    extern __shared__ char sm[];
    float* win   = (float*)(sm + OFF_WIN);   // [192][32] t-major
    float* scr   = (float*)(sm + OFF_SCR);   // [64][32]
    float* wcomb = (float*)(sm + OFF_MISC);  // [65]
    float* bcs   = wcomb + 65;
    float* dsh   = wcomb + 66;               // [32]

    const int tid  = threadIdx.x;
    const int b0g  = blockIdx.x * 32;
    const int warp = tid >> 5, lane = tid & 31;
    const int g    = lane >> 2, tg = lane & 3;
    const int q    = 4*warp + (g & 3);                 // this thread's unit
    const bool glo = (g < 4);
    const int bb0  = (glo ? 0 : 16) + 2*tg;            // batches bb0,bb0+1,bb0+8,bb0+9
    const int rowA = (g >> 2)*64 + 4*warp + (g & 3);   // W row for C-tile row g (g+8 -> rowA+128)

    const u32 hsm0 = (u32)__cvta_generic_to_shared(sm + OFF_H);
    const u32 laneoff = (u32)((lane & 7) * PB + ((lane >> 3) & 1) * (8 * PB) + (lane >> 4) * 16);

    // ---- one-time init ----
    for (int i = tid; i < TLEN*32; i += NTHR) {
        int t = i >> 5, b = i & 31;
        win[t*32 + b] = x[(size_t)(b0g + b)*SEQ + t];
    }
    if (tid < 32) dsh[tid] = x[(size_t)(b0g + tid)*SEQ + TLEN];
    if (tid < 65) {
        float s = 0.0f;
        for (int j = 0; j < 64; j++) s = fmaf(fc2w[j], fc1w[j*65 + tid], s);
        wcomb[tid] = s;
    }
    if (tid == 65) {
        float s = fc2b[0];
        for (int j = 0; j < 64; j++) s = fmaf(fc2w[j], fc1b[j], s);
        *bcs = s;
    }
    float wi1f[4], b1f[4], b2f[4];
    #pragma unroll
    for (int ga = 0; ga < 4; ga++) {
        wi1f[ga] = Wih1[ga*64 + q];
        b1f[ga]  = bih1[ga*64 + q] + bhh1[ga*64 + q];
        b2f[ga]  = bih2[ga*64 + q] + bhh2[ga*64 + q];
    }
    u16* r1h = g_r1h + (size_t)blockIdx.x * TLEN * 2048;
    u16* r1l = g_r1l + (size_t)blockIdx.x * TLEN * 2048;

    u32 Ahi[8][4], Alo[8][4];
    float cst[4], hl[4];
    u32 r1nh0, r1nh1, r1nl0, r1nl1;

    for (int step = 0; step < NSTEPS; step++) {
        // ---- stage A regs from Whh1 (K=64) ----
        #pragma unroll
        for (int kk = 0; kk < 4; kk++) {
            int k1 = 16*kk + 2*tg, k2 = k1 + 8;
            float2 vA1 = *(const float2*)(Whh1 + rowA*64 + k1);
            float2 vB1 = *(const float2*)(Whh1 + (rowA+128)*64 + k1);
            float2 vA2 = *(const float2*)(Whh1 + rowA*64 + k2);
            float2 vB2 = *(const float2*)(Whh1 + (rowA+128)*64 + k2);
            splitpack(vA1.x, vA1.y, Ahi[kk][0], Alo[kk][0]);
            splitpack(vB1.x, vB1.y, Ahi[kk][1], Alo[kk][1]);
            splitpack(vA2.x, vA2.y, Ahi[kk][2], Alo[kk][2]);
            splitpack(vB2.x, vB2.y, Ahi[kk][3], Alo[kk][3]);
        }
        // zero H buf0
        for (int i = tid; i < HBUFB/4; i += NTHR) ((u32*)(sm + OFF_H))[i] = 0u;
        cst[0] = cst[1] = cst[2] = cst[3] = 0.0f;
        __syncthreads();

        // ================= layer 1 =================
        for (int t = 0; t < TLEN; t++) {
            float c[4][4];
            #pragma unroll
            for (int n = 0; n < 4; n++) { c[n][0]=c[n][1]=c[n][2]=c[n][3]=0.0f; }
            do_mma<4>(hsm0 + (t&1)*HBUFB + laneoff, Ahi, Alo, c);
            float rx[2][4];
            #pragma unroll
            for (int n2 = 0; n2 < 2; n2++)
                #pragma unroll
                for (int j = 0; j < 4; j++) {
                    float send = glo ? c[2+n2][j] : c[n2][j];
                    rx[n2][j] = __shfl_xor_sync(0xffffffffu, send, 16);
                }
            float2 xv0 = *(const float2*)(win + (step+t)*32 + bb0);
            float2 xv1 = *(const float2*)(win + (step+t)*32 + bb0 + 8);
            float xa[4] = {xv0.x, xv0.y, xv1.x, xv1.y};
            u16 hh_[4], ll_[4], rh_[4], rl_[4];
            #pragma unroll
            for (int j = 0; j < 4; j++) {
                int n2 = j >> 1, col = j & 1;
                float gi = glo ? c[n2][col]     : rx[n2][col];
                float gg = glo ? c[n2][2+col]   : rx[n2][2+col];
                float f  = glo ? rx[n2][col]    : c[2+n2][col];
                float o  = glo ? rx[n2][2+col]  : c[2+n2][2+col];
                gi += fmaf(xa[j], wi1f[0], b1f[0]);
                f  += fmaf(xa[j], wi1f[1], b1f[1]);
                gg += fmaf(xa[j], wi1f[2], b1f[2]);
                o  += fmaf(xa[j], wi1f[3], b1f[3]);
                float cn = fmaf(sigf(f), cst[j], sigf(gi)*tanhf_(gg));
                cst[j] = cn;
                float h = sigf(o)*tanhf_(cn);
                hl[j] = h;
                split1(h, hh_[j], ll_[j]);
                split1(fmaxf(h, 0.0f), rh_[j], rl_[j]);
            }
            char* hw = sm + OFF_H + ((t+1)&1)*HBUFB;
            *(u32*)(hw + q*PB + 2*bb0)            = (u32)hh_[0] | ((u32)hh_[1] << 16);
            *(u32*)(hw + q*PB + 2*bb0 + 16)       = (u32)hh_[2] | ((u32)hh_[3] << 16);
            *(u32*)(hw + (128+q)*PB + 2*bb0)      = (u32)ll_[0] | ((u32)ll_[1] << 16);
            *(u32*)(hw + (128+q)*PB + 2*bb0 + 16) = (u32)ll_[2] | ((u32)ll_[3] << 16);
            size_t ri = (size_t)t*2048 + q*32 + bb0;
            *(u32*)(r1h + ri)     = (u32)rh_[0] | ((u32)rh_[1] << 16);
            *(u32*)(r1h + ri + 8) = (u32)rh_[2] | ((u32)rh_[3] << 16);
            *(u32*)(r1l + ri)     = (u32)rl_[0] | ((u32)rl_[1] << 16);
            *(u32*)(r1l + ri + 8) = (u32)rl_[2] | ((u32)rl_[3] << 16);
            __syncthreads();
        }

        // ---- stage A regs for layer 2 (K=128: Wih2 | Whh2) ----
        #pragma unroll
        for (int kk = 0; kk < 8; kk++) {
            const float* W = (kk < 4) ? Wih2 : Whh2;
            int k1 = 16*(kk & 3) + 2*tg, k2 = k1 + 8;
            float2 vA1 = *(const float2*)(W + rowA*64 + k1);
            float2 vB1 = *(const float2*)(W + (rowA+128)*64 + k1);
            float2 vA2 = *(const float2*)(W + rowA*64 + k2);
            float2 vB2 = *(const float2*)(W + (rowA+128)*64 + k2);
            splitpack(vA1.x, vA1.y, Ahi[kk][0], Alo[kk][0]);
            splitpack(vB1.x, vB1.y, Ahi[kk][1], Alo[kk][1]);
            splitpack(vA2.x, vA2.y, Ahi[kk][2], Alo[kk][2]);
            splitpack(vB2.x, vB2.y, Ahi[kk][3], Alo[kk][3]);
        }
        // ---- transition into buf0: rows 64+q h1_T, rows q = r1(0); prefetch r1(1) ----
        {
            char* h0 = sm + OFF_H;
            u16 hh_[4], ll_[4];
            #pragma unroll
            for (int j = 0; j < 4; j++) split1(hl[j], hh_[j], ll_[j]);
            *(u32*)(h0 + (64+q)*PB + 2*bb0)       = (u32)hh_[0] | ((u32)hh_[1] << 16);
            *(u32*)(h0 + (64+q)*PB + 2*bb0 + 16)  = (u32)hh_[2] | ((u32)hh_[3] << 16);
            *(u32*)(h0 + (192+q)*PB + 2*bb0)      = (u32)ll_[0] | ((u32)ll_[1] << 16);
            *(u32*)(h0 + (192+q)*PB + 2*bb0 + 16) = (u32)ll_[2] | ((u32)ll_[3] << 16);
            size_t ri = (size_t)q*32 + bb0;
            *(u32*)(h0 + q*PB + 2*bb0)            = *(const u32*)(r1h + ri);
            *(u32*)(h0 + q*PB + 2*bb0 + 16)       = *(const u32*)(r1h + ri + 8);
            *(u32*)(h0 + (128+q)*PB + 2*bb0)      = *(const u32*)(r1l + ri);
            *(u32*)(h0 + (128+q)*PB + 2*bb0 + 16) = *(const u32*)(r1l + ri + 8);
            r1nh0 = *(const u32*)(r1h + 2048 + ri);
            r1nh1 = *(const u32*)(r1h + 2048 + ri + 8);
            r1nl0 = *(const u32*)(r1l + 2048 + ri);
            r1nl1 = *(const u32*)(r1l + 2048 + ri + 8);
        }
        __syncthreads();

        // ================= layer 2 =================
        for (int t = 0; t < TLEN; t++) {
            float c[4][4];
            #pragma unroll
            for (int n = 0; n < 4; n++) { c[n][0]=c[n][1]=c[n][2]=c[n][3]=0.0f; }
            do_mma<8>(hsm0 + (t&1)*HBUFB + laneoff, Ahi, Alo, c);
            float rx[2][4];
            #pragma unroll
            for (int n2 = 0; n2 < 2; n2++)
                #pragma unroll
                for (int j = 0; j < 4; j++) {
                    float send = glo ? c[2+n2][j] : c[n2][j];
                    rx[n2][j] = __shfl_xor_sync(0xffffffffu, send, 16);
                }
            u16 hh_[4], ll_[4];
            float hcur[4];
            #pragma unroll
            for (int j = 0; j < 4; j++) {
                int n2 = j >> 1, col = j & 1;
                float gi = (glo ? c[n2][col]    : rx[n2][col])    + b2f[0];
                float f  = (glo ? rx[n2][col]   : c[2+n2][col])   + b2f[1];
                float gg = (glo ? c[n2][2+col]  : rx[n2][2+col])  + b2f[2];
                float o  = (glo ? rx[n2][2+col] : c[2+n2][2+col]) + b2f[3];
                float cn = fmaf(sigf(f), cst[j], sigf(gi)*tanhf_(gg));
                cst[j] = cn;
                hcur[j] = sigf(o)*tanhf_(cn);
                split1(hcur[j], hh_[j], ll_[j]);
            }
            if (t + 1 < TLEN) {
                char* hw = sm + OFF_H + ((t+1)&1)*HBUFB;
                *(u32*)(hw + (64+q)*PB + 2*bb0)       = (u32)hh_[0] | ((u32)hh_[1] << 16);
                *(u32*)(hw + (64+q)*PB + 2*bb0 + 16)  = (u32)hh_[2] | ((u32)hh_[3] << 16);
                *(u32*)(hw + (192+q)*PB + 2*bb0)      = (u32)ll_[0] | ((u32)ll_[1] << 16);
                *(u32*)(hw + (192+q)*PB + 2*bb0 + 16) = (u32)ll_[2] | ((u32)ll_[3] << 16);
                *(u32*)(hw + q*PB + 2*bb0)            = r1nh0;
                *(u32*)(hw + q*PB + 2*bb0 + 16)       = r1nh1;
                *(u32*)(hw + (128+q)*PB + 2*bb0)      = r1nl0;
                *(u32*)(hw + (128+q)*PB + 2*bb0 + 16) = r1nl1;
                if (t + 2 < TLEN) {
                    size_t ri = (size_t)(t+2)*2048 + q*32 + bb0;
                    r1nh0 = *(const u32*)(r1h + ri);
                    r1nh1 = *(const u32*)(r1h + ri + 8);
                    r1nl0 = *(const u32*)(r1l + ri);
                    r1nl1 = *(const u32*)(r1l + ri + 8);
                }
            } else {
                *(float2*)(scr + q*32 + bb0)     = make_float2(fmaxf(hcur[0],0.0f), fmaxf(hcur[1],0.0f));
                *(float2*)(scr + q*32 + bb0 + 8) = make_float2(fmaxf(hcur[2],0.0f), fmaxf(hcur[3],0.0f));
            }
            __syncthreads();
        }

        // ---- FC (collapsed) + window append ----
        if (tid < 32) {
            float s = *bcs + wcomb[64] * dsh[tid];
            #pragma unroll
            for (int uu = 0; uu < 64; uu++)
                s = fmaf(wcomb[uu], scr[uu*32 + tid], s);
            out[(size_t)(b0g + tid)*NSTEPS + step] = s;
            win[(TLEN + step)*32 + tid] = s;
        }
        __syncthreads();
    }
}

extern "C" void kernel_launch(void* const* d_in, const int* in_sizes, int n_in,
                              void* d_out, int out_size) {
    (void)in_sizes; (void)n_in; (void)out_size;
    const float* x    = (const float*)d_in[0];
    const float* Wih1 = (const float*)d_in[1];
    const float* Whh1 = (const float*)d_in[2];
    const float* bih1 = (const float*)d_in[3];
    const float* bhh1 = (const float*)d_in[4];
    const float* Wih2 = (const float*)d_in[5];
    const float* Whh2 = (const float*)d_in[6];
    const float* bih2 = (const float*)d_in[7];
    const float* bhh2 = (const float*)d_in[8];
    const float* fc1w = (const float*)d_in[9];
    const float* fc1b = (const float*)d_in[10];
    const float* fc2w = (const float*)d_in[11];
    const float* fc2b = (const float*)d_in[12];
    float* out = (float*)d_out;

    cudaFuncSetAttribute(lstm_rec_kernel, cudaFuncAttributeMaxDynamicSharedMemorySize, SMEM_BYTES);
    lstm_rec_kernel<<<GRID, NTHR, SMEM_BYTES>>>(x, Wih1, Whh1, bih1, bhh1,
                                                Wih2, Whh2, bih2, bhh2,
                                                fc1w, fc1b, fc2w, fc2b, out);
}

// round 13
// speedup vs baseline: 2.1402x; 1.0114x over previous
#include <cuda_runtime.h>
#include <cuda_bf16.h>

typedef unsigned int u32;
typedef unsigned short u16;
typedef unsigned long long u64;

#define GRID   128
#define NTHR   512
#define TLEN   168
#define SEQ    169
#define NSTEPS 24
#define PB     80                 // H row pitch in bytes
#define HBUFB  (256 * PB)         // one H buffer (rows 0-127 hi, 128-255 lo)

#define OFF_H    0
#define OFF_WIN  (2 * HBUFB)
#define OFF_SCR  (OFF_WIN + 192*32*4)
#define OFF_MISC (OFF_SCR + 64*32*4)
#define SMEM_BYTES (OFF_MISC + 512)

// r1 staging, separate bf16 hi / lo planes: [GRID][TLEN][64 units][32 batches]
__device__ u16 g_r1h[(size_t)GRID * TLEN * 64 * 32];
__device__ u16 g_r1l[(size_t)GRID * TLEN * 64 * 32];

static __device__ __forceinline__ float rcpf(float x){float r;asm("rcp.approx.f32 %0,%1;":"=f"(r):"f"(x));return r;}
static __device__ __forceinline__ float sigf(float x){return rcpf(1.0f+__expf(-x));}
static __device__ __forceinline__ float tanhf_(float x){return fmaf(2.0f,sigf(2.0f*x),-1.0f);}

// hi = truncated top-16 pair (PRMT), lo = rn(bf16) of remainders, packed
static __device__ __forceinline__ void splitpack2(float x0,float x1,u32&hi,u32&lo){
    u32 a=__float_as_uint(x0), b=__float_as_uint(x1);
    asm("prmt.b32 %0,%1,%2,0x7632;":"=r"(hi):"r"(a),"r"(b));
    float r0=x0-__uint_as_float(a&0xffff0000u);
    float r1=x1-__uint_as_float(b&0xffff0000u);
    asm("cvt.rn.bf16x2.f32 %0,%1,%2;":"=r"(lo):"f"(r1),"f"(r0));
}
static __device__ __forceinline__ void mma4(float c[4],const u32 a[4],u32 b0,u32 b1){
    asm volatile("mma.sync.aligned.m16n8k16.row.col.f32.bf16.bf16.f32 "
        "{%0,%1,%2,%3},{%4,%5,%6,%7},{%8,%9},{%0,%1,%2,%3};"
        :"+f"(c[0]),"+f"(c[1]),"+f"(c[2]),"+f"(c[3])
        :"r"(a[0]),"r"(a[1]),"r"(a[2]),"r"(a[3]),"r"(b0),"r"(b1));
}
static __device__ __forceinline__ void ldm4t(u32 addr,u32&r0,u32&r1,u32&r2,u32&r3){
    asm volatile("ldmatrix.sync.aligned.m8n8.x4.trans.shared.b16 {%0,%1,%2,%3}, [%4];"
        :"=r"(r0),"=r"(r1),"=r"(r2),"=r"(r3):"r"(addr));
}

// half-batch GEMM (2 n-tiles), 3-pass split precision. toff: 0 = tiles 0,1; 32 = tiles 2,3
template<int KK>
static __device__ __forceinline__ void mma_half(u32 hb, u32 toff,
                                                const u32 Ahi[8][4], const u32 Alo[8][4],
                                                float c[2][4])
{
    #pragma unroll
    for (int kk = 0; kk < KK; kk++) {
        u32 a0 = hb + (u32)(kk * 16 * PB) + toff;
        u32 b0,b1,b2,b3, l0,l1,l2,l3;
        ldm4t(a0,          b0,b1,b2,b3);
        ldm4t(a0+128*PB,   l0,l1,l2,l3);
        mma4(c[0], Ahi[kk], b0, b1);
        mma4(c[1], Ahi[kk], b2, b3);
        mma4(c[0], Ahi[kk], l0, l1);
        mma4(c[1], Ahi[kk], l2, l3);
        mma4(c[0], Alo[kk], b0, b1);
        mma4(c[1], Alo[kk], b2, b3);
    }
}

__global__ void __launch_bounds__(NTHR, 1)
lstm_rec_kernel(const float* __restrict__ x,
                const float* __restrict__ Wih1, const float* __restrict__ Whh1,
                const float* __restrict__ bih1, const float* __restrict__ bhh1,
                const float* __restrict__ Wih2, const float* __restrict__ Whh2,
                const float* __restrict__ bih2, const float* __restrict__ bhh2,
                const float* __restrict__ fc1w, const float* __restrict__ fc1b,
                const float* __restrict__ fc2w, const float* __restrict__ fc2b,
                float* __restrict__ out)
{
    extern __shared__ char sm[];
    float* win   = (float*)(sm + OFF_WIN);   // [192][32] t-major
    float* scr   = (float*)(sm + OFF_SCR);   // [64][32]
    float* wcomb = (float*)(sm + OFF_MISC);  // [65]
    float* bcs   = wcomb + 65;
    float* dsh   = wcomb + 66;               // [32]

    const int tid  = threadIdx.x;
    const int b0g  = blockIdx.x * 32;
    const int warp = tid >> 5, lane = tid & 31;
    const int g    = lane >> 2, tg = lane & 3;
    const int q    = 4*warp + (g & 3);                 // this thread's unit
    const bool glo = (g < 4);
    const int bA0  = (glo ? 0 : 8) + 2*tg;             // phase-A batches bA0,bA0+1
    const int bB0  = bA0 + 16;                         // phase-B batches
    const int rowA = (g >> 2)*64 + 4*warp + (g & 3);   // W row for C-tile row g

    const u32 hsm0 = (u32)__cvta_generic_to_shared(sm + OFF_H);
    const u32 laneoff = (u32)((lane & 7) * PB + ((lane >> 3) & 1) * (8 * PB) + (lane >> 4) * 16);

    // ---- one-time init ----
    for (int i = tid; i < TLEN*32; i += NTHR) {
        int t = i >> 5, b = i & 31;
        win[t*32 + b] = x[(size_t)(b0g + b)*SEQ + t];
    }
    if (tid < 32) dsh[tid] = x[(size_t)(b0g + tid)*SEQ + TLEN];
    if (tid < 65) {
        float s = 0.0f;
        for (int j = 0; j < 64; j++) s = fmaf(fc2w[j], fc1w[j*65 + tid], s);
        wcomb[tid] = s;
    }
    if (tid == 65) {
        float s = fc2b[0];
        for (int j = 0; j < 64; j++) s = fmaf(fc2w[j], fc1b[j], s);
        *bcs = s;
    }
    float wi1f[4], b1f[4], b2f[4];
    #pragma unroll
    for (int ga = 0; ga < 4; ga++) {
        wi1f[ga] = Wih1[ga*64 + q];
        b1f[ga]  = bih1[ga*64 + q] + bhh1[ga*64 + q];
        b2f[ga]  = bih2[ga*64 + q] + bhh2[ga*64 + q];
    }
    u16* r1h = g_r1h + (size_t)blockIdx.x * TLEN * 2048;
    u16* r1l = g_r1l + (size_t)blockIdx.x * TLEN * 2048;

    u32 Ahi[8][4], Alo[8][4];
    float cst[4], hl[4];
    float cA[2][4], cB[2][4];
    u32 r1AH, r1AL, r1BH, r1BL;

    for (int step = 0; step < NSTEPS; step++) {
        // ---- stage A regs from Whh1 (K=64) ----
        #pragma unroll
        for (int kk = 0; kk < 4; kk++) {
            int k1 = 16*kk + 2*tg, k2 = k1 + 8;
            float2 vA1 = *(const float2*)(Whh1 + rowA*64 + k1);
            float2 vB1 = *(const float2*)(Whh1 + (rowA+128)*64 + k1);
            float2 vA2 = *(const float2*)(Whh1 + rowA*64 + k2);
            float2 vB2 = *(const float2*)(Whh1 + (rowA+128)*64 + k2);
            splitpack2(vA1.x, vA1.y, Ahi[kk][0], Alo[kk][0]);
            splitpack2(vB1.x, vB1.y, Ahi[kk][1], Alo[kk][1]);
            splitpack2(vA2.x, vA2.y, Ahi[kk][2], Alo[kk][2]);
            splitpack2(vB2.x, vB2.y, Ahi[kk][3], Alo[kk][3]);
        }
        // zero H buf0
        for (int i = tid; i < HBUFB/4; i += NTHR) ((u32*)(sm + OFF_H))[i] = 0u;
        cst[0] = cst[1] = cst[2] = cst[3] = 0.0f;
        __syncthreads();

        // ================= layer 1 =================
        #pragma unroll
        for (int n = 0; n < 2; n++) { cA[n][0]=cA[n][1]=cA[n][2]=cA[n][3]=0.0f; }
        mma_half<4>(hsm0 + laneoff, 0, Ahi, Alo, cA);      // mma_A(0), buf0

        for (int t = 0; t < TLEN; t++) {
            // ---- phase 1: mma_B(t) || act_A(t) ----
            #pragma unroll
            for (int n = 0; n < 2; n++) { cB[n][0]=cB[n][1]=cB[n][2]=cB[n][3]=0.0f; }
            mma_half<4>(hsm0 + (t&1)*HBUFB + laneoff, 32, Ahi, Alo, cB);
            {
                float rx[4];
                #pragma unroll
                for (int j = 0; j < 4; j++) {
                    float s = glo ? cA[1][j] : cA[0][j];
                    rx[j] = __shfl_xor_sync(0xffffffffu, s, 16);
                }
                float2 xv = *(const float2*)(win + (step+t)*32 + bA0);
                float xc[2] = {xv.x, xv.y};
                float hv[2], rv[2];
                #pragma unroll
                for (int col = 0; col < 2; col++) {
                    float gi = (glo ? cA[0][col]   : rx[col])      + fmaf(xc[col], wi1f[0], b1f[0]);
                    float f  = (glo ? rx[col]      : cA[1][col])   + fmaf(xc[col], wi1f[1], b1f[1]);
                    float gg = (glo ? cA[0][2+col] : rx[2+col])    + fmaf(xc[col], wi1f[2], b1f[2]);
                    float o  = (glo ? rx[2+col]    : cA[1][2+col]) + fmaf(xc[col], wi1f[3], b1f[3]);
                    float cn = fmaf(sigf(f), cst[col], sigf(gi)*tanhf_(gg));
                    cst[col] = cn;
                    float h = sigf(o)*tanhf_(cn);
                    hl[col] = h; hv[col] = h; rv[col] = fmaxf(h, 0.0f);
                }
                u32 hi, lo; splitpack2(hv[0], hv[1], hi, lo);
                char* hw = sm + OFF_H + ((t+1)&1)*HBUFB;
                *(u32*)(hw + q*PB + 2*bA0)       = hi;
                *(u32*)(hw + (128+q)*PB + 2*bA0) = lo;
                u32 rhi, rlo; splitpack2(rv[0], rv[1], rhi, rlo);
                size_t ri = (size_t)t*2048 + q*32 + bA0;
                *(u32*)(r1h + ri) = rhi; *(u32*)(r1l + ri) = rlo;
            }
            __syncthreads();
            // ---- phase 2: mma_A(t+1) || act_B(t)  (t=T-1: mma result discarded) ----
            #pragma unroll
            for (int n = 0; n < 2; n++) { cA[n][0]=cA[n][1]=cA[n][2]=cA[n][3]=0.0f; }
            mma_half<4>(hsm0 + ((t+1)&1)*HBUFB + laneoff, 0, Ahi, Alo, cA);
            {
                float rx[4];
                #pragma unroll
                for (int j = 0; j < 4; j++) {
                    float s = glo ? cB[1][j] : cB[0][j];
                    rx[j] = __shfl_xor_sync(0xffffffffu, s, 16);
                }
                float2 xv = *(const float2*)(win + (step+t)*32 + bB0);
                float xc[2] = {xv.x, xv.y};
                float hv[2], rv[2];
                #pragma unroll
                for (int col = 0; col < 2; col++) {
                    float gi = (glo ? cB[0][col]   : rx[col])      + fmaf(xc[col], wi1f[0], b1f[0]);
                    float f  = (glo ? rx[col]      : cB[1][col])   + fmaf(xc[col], wi1f[1], b1f[1]);
                    float gg = (glo ? cB[0][2+col] : rx[2+col])    + fmaf(xc[col], wi1f[2], b1f[2]);
                    float o  = (glo ? rx[2+col]    : cB[1][2+col]) + fmaf(xc[col], wi1f[3], b1f[3]);
                    float cn = fmaf(sigf(f), cst[2+col], sigf(gi)*tanhf_(gg));
                    cst[2+col] = cn;
                    float h = sigf(o)*tanhf_(cn);
                    hl[2+col] = h; hv[col] = h; rv[col] = fmaxf(h, 0.0f);
                }
                u32 hi, lo; splitpack2(hv[0], hv[1], hi, lo);
                char* hw = sm + OFF_H + ((t+1)&1)*HBUFB;
                *(u32*)(hw + q*PB + 2*bB0)       = hi;
                *(u32*)(hw + (128+q)*PB + 2*bB0) = lo;
                u32 rhi, rlo; splitpack2(rv[0], rv[1], rhi, rlo);
                size_t ri = (size_t)t*2048 + q*32 + bB0;
                *(u32*)(r1h + ri) = rhi; *(u32*)(r1l + ri) = rlo;
            }
            __syncthreads();
        }

        // ---- stage A regs for layer 2 (K=128: Wih2 | Whh2) ----
        #pragma unroll
        for (int kk = 0; kk < 8; kk++) {
            const float* W = (kk < 4) ? Wih2 : Whh2;
            int k1 = 16*(kk & 3) + 2*tg, k2 = k1 + 8;
            float2 vA1 = *(const float2*)(W + rowA*64 + k1);
            float2 vB1 = *(const float2*)(W + (rowA+128)*64 + k1);
            float2 vA2 = *(const float2*)(W + rowA*64 + k2);
            float2 vB2 = *(const float2*)(W + (rowA+128)*64 + k2);
            splitpack2(vA1.x, vA1.y, Ahi[kk][0], Alo[kk][0]);
            splitpack2(vB1.x, vB1.y, Ahi[kk][1], Alo[kk][1]);
            splitpack2(vA2.x, vA2.y, Ahi[kk][2], Alo[kk][2]);
            splitpack2(vB2.x, vB2.y, Ahi[kk][3], Alo[kk][3]);
        }
        // ---- transition into buf0: rows 64+q = h1_T, rows q = r1(0); prefetch r1(1) ----
        {
            char* h0 = sm + OFF_H;
            u32 hi, lo;
            splitpack2(hl[0], hl[1], hi, lo);
            *(u32*)(h0 + (64+q)*PB + 2*bA0)  = hi;
            *(u32*)(h0 + (192+q)*PB + 2*bA0) = lo;
            splitpack2(hl[2], hl[3], hi, lo);
            *(u32*)(h0 + (64+q)*PB + 2*bB0)  = hi;
            *(u32*)(h0 + (192+q)*PB + 2*bB0) = lo;
            size_t riA = (size_t)q*32 + bA0, riB = (size_t)q*32 + bB0;
            *(u32*)(h0 + q*PB + 2*bA0)       = *(const u32*)(r1h + riA);
            *(u32*)(h0 + (128+q)*PB + 2*bA0) = *(const u32*)(r1l + riA);
            *(u32*)(h0 + q*PB + 2*bB0)       = *(const u32*)(r1h + riB);
            *(u32*)(h0 + (128+q)*PB + 2*bB0) = *(const u32*)(r1l + riB);
            r1AH = *(const u32*)(r1h + 2048 + riA);
            r1AL = *(const u32*)(r1l + 2048 + riA);
            r1BH = *(const u32*)(r1h + 2048 + riB);
            r1BL = *(const u32*)(r1l + 2048 + riB);
        }
        __syncthreads();

        // ================= layer 2 =================
        #pragma unroll
        for (int n = 0; n < 2; n++) { cA[n][0]=cA[n][1]=cA[n][2]=cA[n][3]=0.0f; }
        mma_half<8>(hsm0 + laneoff, 0, Ahi, Alo, cA);      // mma_A(0), buf0

        for (int t = 0; t < TLEN; t++) {
            // ---- phase 1: mma_B(t) || act_B... act_A(t) ----
            #pragma unroll
            for (int n = 0; n < 2; n++) { cB[n][0]=cB[n][1]=cB[n][2]=cB[n][3]=0.0f; }
            mma_half<8>(hsm0 + (t&1)*HBUFB + laneoff, 32, Ahi, Alo, cB);
            {
                float rx[4];
                #pragma unroll
                for (int j = 0; j < 4; j++) {
                    float s = glo ? cA[1][j] : cA[0][j];
                    rx[j] = __shfl_xor_sync(0xffffffffu, s, 16);
                }
                float hv[2];
                #pragma unroll
                for (int col = 0; col < 2; col++) {
                    float gi = (glo ? cA[0][col]   : rx[col])      + b2f[0];
                    float f  = (glo ? rx[col]      : cA[1][col])   + b2f[1];
                    float gg = (glo ? cA[0][2+col] : rx[2+col])    + b2f[2];
                    float o  = (glo ? rx[2+col]    : cA[1][2+col]) + b2f[3];
                    float cn = fmaf(sigf(f), cst[col], sigf(gi)*tanhf_(gg));
                    cst[col] = cn;
                    hv[col] = sigf(o)*tanhf_(cn);
                }
                if (t + 1 < TLEN) {
                    u32 hi, lo; splitpack2(hv[0], hv[1], hi, lo);
                    char* hw = sm + OFF_H + ((t+1)&1)*HBUFB;
                    *(u32*)(hw + (64+q)*PB + 2*bA0)  = hi;
                    *(u32*)(hw + (192+q)*PB + 2*bA0) = lo;
                    *(u32*)(hw + q*PB + 2*bA0)       = r1AH;
                    *(u32*)(hw + (128+q)*PB + 2*bA0) = r1AL;
                    if (t + 2 < TLEN) {
                        size_t ri = (size_t)(t+2)*2048 + q*32 + bA0;
                        r1AH = *(const u32*)(r1h + ri);
                        r1AL = *(const u32*)(r1l + ri);
                    }
                } else {
                    *(float2*)(scr + q*32 + bA0) =
                        make_float2(fmaxf(hv[0], 0.0f), fmaxf(hv[1], 0.0f));
                }
            }
            __syncthreads();
            // ---- phase 2: mma_A(t+1) || act_B(t) ----
            #pragma unroll
            for (int n = 0; n < 2; n++) { cA[n][0]=cA[n][1]=cA[n][2]=cA[n][3]=0.0f; }
            mma_half<8>(hsm0 + ((t+1)&1)*HBUFB + laneoff, 0, Ahi, Alo, cA);
            {
                float rx[4];
                #pragma unroll
                for (int j = 0; j < 4; j++) {
                    float s = glo ? cB[1][j] : cB[0][j];
                    rx[j] = __shfl_xor_sync(0xffffffffu, s, 16);
                }
                float hv[2];
                #pragma unroll
                for (int col = 0; col < 2; col++) {
                    float gi = (glo ? cB[0][col]   : rx[col])      + b2f[0];
                    float f  = (glo ? rx[col]      : cB[1][col])   + b2f[1];
                    float gg = (glo ? cB[0][2+col] : rx[2+col])    + b2f[2];
                    float o  = (glo ? rx[2+col]    : cB[1][2+col]) + b2f[3];
                    float cn = fmaf(sigf(f), cst[2+col], sigf(gi)*tanhf_(gg));
                    cst[2+col] = cn;
                    hv[col] = sigf(o)*tanhf_(cn);
                }
                if (t + 1 < TLEN) {
                    u32 hi, lo; splitpack2(hv[0], hv[1], hi, lo);
                    char* hw = sm + OFF_H + ((t+1)&1)*HBUFB;
                    *(u32*)(hw + (64+q)*PB + 2*bB0)  = hi;
                    *(u32*)(hw + (192+q)*PB + 2*bB0) = lo;
                    *(u32*)(hw + q*PB + 2*bB0)       = r1BH;
                    *(u32*)(hw + (128+q)*PB + 2*bB0) = r1BL;
                    if (t + 2 < TLEN) {
                        size_t ri = (size_t)(t+2)*2048 + q*32 + bB0;
                        r1BH = *(const u32*)(r1h + ri);
                        r1BL = *(const u32*)(r1l + ri);
                    }
                } else {
                    *(float2*)(scr + q*32 + bB0) =
                        make_float2(fmaxf(hv[0], 0.0f), fmaxf(hv[1], 0.0f));
                }
            }
            __syncthreads();
        }

        // ---- FC (collapsed) + window append ----
        if (tid < 32) {
            float s = *bcs + wcomb[64] * dsh[tid];
            #pragma unroll
            for (int uu = 0; uu < 64; uu++)
                s = fmaf(wcomb[uu], scr[uu*32 + tid], s);
            out[(size_t)(b0g + tid)*NSTEPS + step] = s;
            win[(TLEN + step)*32 + tid] = s;
        }
        __syncthreads();
    }
}

extern "C" void kernel_launch(void* const* d_in, const int* in_sizes, int n_in,
                              void* d_out, int out_size) {
    (void)in_sizes; (void)n_in; (void)out_size;
    const float* x    = (const float*)d_in[0];
    const float* Wih1 = (const float*)d_in[1];
    const float* Whh1 = (const float*)d_in[2];
    const float* bih1 = (const float*)d_in[3];
    const float* bhh1 = (const float*)d_in[4];
    const float* Wih2 = (const float*)d_in[5];
    const float* Whh2 = (const float*)d_in[6];
    const float* bih2 = (const float*)d_in[7];
    const float* bhh2 = (const float*)d_in[8];
    const float* fc1w = (const float*)d_in[9];
    const float* fc1b = (const float*)d_in[10];
    const float* fc2w = (const float*)d_in[11];
    const float* fc2b = (const float*)d_in[12];
    float* out = (float*)d_out;

    cudaFuncSetAttribute(lstm_rec_kernel, cudaFuncAttributeMaxDynamicSharedMemorySize, SMEM_BYTES);
    lstm_rec_kernel<<<GRID, NTHR, SMEM_BYTES>>>(x, Wih1, Whh1, bih1, bhh1,
                                                Wih2, Whh2, bih2, bhh2,
                                                fc1w, fc1b, fc2w, fc2b, out);
}

// round 14
// speedup vs baseline: 2.5108x; 1.1732x over previous
#include <cuda_runtime.h>
#include <cuda_bf16.h>

typedef unsigned int u32;
typedef unsigned short u16;
typedef unsigned long long u64;

#define GRID   128
#define NTHR   512
#define TLEN   168
#define SEQ    169
#define NSTEPS 24
#define PB     80                 // H row pitch in bytes
#define HBUFB  (256 * PB)         // one H buffer (rows 0-127 hi, 128-255 lo)

#define OFF_H    0
#define OFF_ALO  (2 * HBUFB)                  // 40960: Alo frags [8 kk][512 tid][16B] = 64KB
#define OFF_WIN  (OFF_ALO + 65536)            // 106496
#define OFF_SCR  (OFF_WIN + 192*32*4)         // 131072
#define OFF_MISC (OFF_SCR + 64*32*4)          // 139264
#define SMEM_BYTES (OFF_MISC + 512)           // 139776

// r1 staging, separate bf16 hi / lo planes: [GRID][TLEN][64 units][32 batches]
__device__ u16 g_r1h[(size_t)GRID * TLEN * 64 * 32];
__device__ u16 g_r1l[(size_t)GRID * TLEN * 64 * 32];

static __device__ __forceinline__ float rcpf(float x){float r;asm("rcp.approx.f32 %0,%1;":"=f"(r):"f"(x));return r;}
static __device__ __forceinline__ float sigf(float x){return rcpf(1.0f+__expf(-x));}
static __device__ __forceinline__ float tanhf_(float x){return fmaf(2.0f,sigf(2.0f*x),-1.0f);}

// hi = truncated top-16 pair (PRMT), lo = rn(bf16) of remainders, packed
static __device__ __forceinline__ void splitpack2(float x0,float x1,u32&hi,u32&lo){
    u32 a=__float_as_uint(x0), b=__float_as_uint(x1);
    asm("prmt.b32 %0,%1,%2,0x7632;":"=r"(hi):"r"(a),"r"(b));
    float r0=x0-__uint_as_float(a&0xffff0000u);
    float r1=x1-__uint_as_float(b&0xffff0000u);
    asm("cvt.rn.bf16x2.f32 %0,%1,%2;":"=r"(lo):"f"(r1),"f"(r0));
}
static __device__ __forceinline__ void mma4(float c[4],const u32 a[4],u32 b0,u32 b1){
    asm volatile("mma.sync.aligned.m16n8k16.row.col.f32.bf16.bf16.f32 "
        "{%0,%1,%2,%3},{%4,%5,%6,%7},{%8,%9},{%0,%1,%2,%3};"
        :"+f"(c[0]),"+f"(c[1]),"+f"(c[2]),"+f"(c[3])
        :"r"(a[0]),"r"(a[1]),"r"(a[2]),"r"(a[3]),"r"(b0),"r"(b1));
}
static __device__ __forceinline__ void ldm4t(u32 addr,u32&r0,u32&r1,u32&r2,u32&r3){
    asm volatile("ldmatrix.sync.aligned.m8n8.x4.trans.shared.b16 {%0,%1,%2,%3}, [%4];"
        :"=r"(r0),"=r"(r1),"=r"(r2),"=r"(r3):"r"(addr));
}
static __device__ __forceinline__ void lds128(u32 addr,u32 r[4]){
    asm volatile("ld.shared.v4.u32 {%0,%1,%2,%3}, [%4];"
        :"=r"(r[0]),"=r"(r[1]),"=r"(r[2]),"=r"(r[3]):"r"(addr));
}

// split-precision GEMM, 2 independent accumulator groups:
// cP += Whi*Hhi + Wlo*Hhi ; cQ += Whi*Hlo
template<int KK>
static __device__ __forceinline__ void do_mma(u32 hb, u32 alo0,
                                              const u32 Ahi[8][4],
                                              float cP[4][4], float cQ[4][4])
{
    #pragma unroll
    for (int kk = 0; kk < KK; kk++) {
        u32 a0 = hb + (u32)(kk * 16 * PB);
        u32 al[4];
        lds128(alo0 + (u32)(kk * 8192), al);
        u32 b0,b1,b2,b3,b4,b5,b6,b7;
        u32 l0,l1,l2,l3,l4,l5,l6,l7;
        ldm4t(a0,              b0,b1,b2,b3);
        ldm4t(a0+32,           b4,b5,b6,b7);
        ldm4t(a0+128*PB,       l0,l1,l2,l3);
        ldm4t(a0+128*PB+32,    l4,l5,l6,l7);
        // pass 1: Whi x Hhi -> cP   (distance-4 per accumulator)
        mma4(cP[0], Ahi[kk], b0, b1);
        mma4(cP[1], Ahi[kk], b2, b3);
        mma4(cP[2], Ahi[kk], b4, b5);
        mma4(cP[3], Ahi[kk], b6, b7);
        // pass 2: Whi x Hlo -> cQ
        mma4(cQ[0], Ahi[kk], l0, l1);
        mma4(cQ[1], Ahi[kk], l2, l3);
        mma4(cQ[2], Ahi[kk], l4, l5);
        mma4(cQ[3], Ahi[kk], l6, l7);
        // pass 3: Wlo x Hhi -> cP   (cP gap = 8)
        mma4(cP[0], al, b0, b1);
        mma4(cP[1], al, b2, b3);
        mma4(cP[2], al, b4, b5);
        mma4(cP[3], al, b6, b7);
    }
}

__global__ void __launch_bounds__(NTHR, 1)
lstm_rec_kernel(const float* __restrict__ x,
                const float* __restrict__ Wih1, const float* __restrict__ Whh1,
                const float* __restrict__ bih1, const float* __restrict__ bhh1,
                const float* __restrict__ Wih2, const float* __restrict__ Whh2,
                const float* __restrict__ bih2, const float* __restrict__ bhh2,
                const float* __restrict__ fc1w, const float* __restrict__ fc1b,
                const float* __restrict__ fc2w, const float* __restrict__ fc2b,
                float* __restrict__ out)
{
    extern __shared__ char sm[];
    float* win   = (float*)(sm + OFF_WIN);   // [192][32] t-major
    float* scr   = (float*)(sm + OFF_SCR);   // [64][32]
    float* wcomb = (float*)(sm + OFF_MISC);  // [65]
    float* bcs   = wcomb + 65;
    float* dsh   = wcomb + 66;               // [32]
    u32*   alo_s = (u32*)(sm + OFF_ALO);

    const int tid  = threadIdx.x;
    const int b0g  = blockIdx.x * 32;
    const int warp = tid >> 5, lane = tid & 31;
    const int g    = lane >> 2, tg = lane & 3;
    const int q    = 4*warp + (g & 3);                 // this thread's unit
    const bool glo = (g < 4);
    const int bb0  = (glo ? 0 : 16) + 2*tg;            // batches bb0,bb0+1,bb0+8,bb0+9
    const int rowA = (g >> 2)*64 + 4*warp + (g & 3);   // W row for C-tile row g

    const u32 hsm0 = (u32)__cvta_generic_to_shared(sm + OFF_H);
    const u32 alo0 = (u32)__cvta_generic_to_shared(alo_s) + (u32)tid * 16;
    const u32 laneoff = (u32)((lane & 7) * PB + ((lane >> 3) & 1) * (8 * PB) + (lane >> 4) * 16);

    // ---- one-time init ----
    for (int i = tid; i < TLEN*32; i += NTHR) {
        int t = i >> 5, b = i & 31;
        win[t*32 + b] = x[(size_t)(b0g + b)*SEQ + t];
    }
    if (tid < 32) dsh[tid] = x[(size_t)(b0g + tid)*SEQ + TLEN];
    if (tid < 65) {
        float s = 0.0f;
        for (int j = 0; j < 64; j++) s = fmaf(fc2w[j], fc1w[j*65 + tid], s);
        wcomb[tid] = s;
    }
    if (tid == 65) {
        float s = fc2b[0];
        for (int j = 0; j < 64; j++) s = fmaf(fc2w[j], fc1b[j], s);
        *bcs = s;
    }
    float wi1f[4], b1f[4], b2f[4];
    #pragma unroll
    for (int ga = 0; ga < 4; ga++) {
        wi1f[ga] = Wih1[ga*64 + q];
        b1f[ga]  = bih1[ga*64 + q] + bhh1[ga*64 + q];
        b2f[ga]  = bih2[ga*64 + q] + bhh2[ga*64 + q];
    }
    u16* r1h = g_r1h + (size_t)blockIdx.x * TLEN * 2048;
    u16* r1l = g_r1l + (size_t)blockIdx.x * TLEN * 2048;

    u32 Ahi[8][4];
    float cst[4], hl[4];
    u32 r1nh0, r1nh1, r1nl0, r1nl1;

    for (int step = 0; step < NSTEPS; step++) {
        // ---- stage A from Whh1 (K=64): hi in regs, lo frags to smem ----
        #pragma unroll
        for (int kk = 0; kk < 4; kk++) {
            int k1 = 16*kk + 2*tg, k2 = k1 + 8;
            float2 vA1 = *(const float2*)(Whh1 + rowA*64 + k1);
            float2 vB1 = *(const float2*)(Whh1 + (rowA+128)*64 + k1);
            float2 vA2 = *(const float2*)(Whh1 + rowA*64 + k2);
            float2 vB2 = *(const float2*)(Whh1 + (rowA+128)*64 + k2);
            u32 lo[4];
            splitpack2(vA1.x, vA1.y, Ahi[kk][0], lo[0]);
            splitpack2(vB1.x, vB1.y, Ahi[kk][1], lo[1]);
            splitpack2(vA2.x, vA2.y, Ahi[kk][2], lo[2]);
            splitpack2(vB2.x, vB2.y, Ahi[kk][3], lo[3]);
            *(uint4*)(alo_s + (kk*512 + tid)*4) = make_uint4(lo[0], lo[1], lo[2], lo[3]);
        }
        // zero H buf0
        for (int i = tid; i < HBUFB/4; i += NTHR) ((u32*)(sm + OFF_H))[i] = 0u;
        cst[0] = cst[1] = cst[2] = cst[3] = 0.0f;
        __syncthreads();

        // ================= layer 1 =================
        for (int t = 0; t < TLEN; t++) {
            float cP[4][4], cQ[4][4];
            #pragma unroll
            for (int n = 0; n < 4; n++)
                #pragma unroll
                for (int j = 0; j < 4; j++) { cP[n][j] = 0.0f; cQ[n][j] = 0.0f; }
            do_mma<4>(hsm0 + (t&1)*HBUFB + laneoff, alo0, Ahi, cP, cQ);
            float c[4][4];
            #pragma unroll
            for (int n = 0; n < 4; n++)
                #pragma unroll
                for (int j = 0; j < 4; j++) c[n][j] = cP[n][j] + cQ[n][j];
            float rx[2][4];
            #pragma unroll
            for (int n2 = 0; n2 < 2; n2++)
                #pragma unroll
                for (int j = 0; j < 4; j++) {
                    float send = glo ? c[2+n2][j] : c[n2][j];
                    rx[n2][j] = __shfl_xor_sync(0xffffffffu, send, 16);
                }
            float2 xv0 = *(const float2*)(win + (step+t)*32 + bb0);
            float2 xv1 = *(const float2*)(win + (step+t)*32 + bb0 + 8);
            float xa[4] = {xv0.x, xv0.y, xv1.x, xv1.y};
            u16 hh_[4], ll_[4], rh_[4], rl_[4];
            #pragma unroll
            for (int j = 0; j < 4; j++) {
                int n2 = j >> 1, col = j & 1;
                float gi = glo ? c[n2][col]     : rx[n2][col];
                float gg = glo ? c[n2][2+col]   : rx[n2][2+col];
                float f  = glo ? rx[n2][col]    : c[2+n2][col];
                float o  = glo ? rx[n2][2+col]  : c[2+n2][2+col];
                gi += fmaf(xa[j], wi1f[0], b1f[0]);
                f  += fmaf(xa[j], wi1f[1], b1f[1]);
                gg += fmaf(xa[j], wi1f[2], b1f[2]);
                o  += fmaf(xa[j], wi1f[3], b1f[3]);
                float cn = fmaf(sigf(f), cst[j], sigf(gi)*tanhf_(gg));
                cst[j] = cn;
                float h = sigf(o)*tanhf_(cn);
                hl[j] = h;
                u32 phl, pll;
                // pack pairs at the end below; temp store per element
                __nv_bfloat16 bh = __float2bfloat16_rn(0.0f); (void)bh; (void)phl; (void)pll;
                u32 dummy; (void)dummy;
                // split via splitpack2 done pairwise after loop
                hh_[j] = 0; ll_[j] = 0; rh_[j] = 0; rl_[j] = 0;
            }
            // pairwise packing (batches j=0,1 and j=2,3 are adjacent columns)
            u32 hA, lA, hB, lB, rhA, rlA, rhB, rlB;
            splitpack2(hl[0], hl[1], hA, lA);
            splitpack2(hl[2], hl[3], hB, lB);
            splitpack2(fmaxf(hl[0],0.0f), fmaxf(hl[1],0.0f), rhA, rlA);
            splitpack2(fmaxf(hl[2],0.0f), fmaxf(hl[3],0.0f), rhB, rlB);
            char* hw = sm + OFF_H + ((t+1)&1)*HBUFB;
            *(u32*)(hw + q*PB + 2*bb0)            = hA;
            *(u32*)(hw + q*PB + 2*bb0 + 16)       = hB;
            *(u32*)(hw + (128+q)*PB + 2*bb0)      = lA;
            *(u32*)(hw + (128+q)*PB + 2*bb0 + 16) = lB;
            size_t ri = (size_t)t*2048 + q*32 + bb0;
            *(u32*)(r1h + ri)     = rhA;
            *(u32*)(r1h + ri + 8) = rhB;
            *(u32*)(r1l + ri)     = rlA;
            *(u32*)(r1l + ri + 8) = rlB;
            __syncthreads();
        }

        // ---- stage A for layer 2 (K=128: Wih2 | Whh2) ----
        #pragma unroll
        for (int kk = 0; kk < 8; kk++) {
            const float* W = (kk < 4) ? Wih2 : Whh2;
            int k1 = 16*(kk & 3) + 2*tg, k2 = k1 + 8;
            float2 vA1 = *(const float2*)(W + rowA*64 + k1);
            float2 vB1 = *(const float2*)(W + (rowA+128)*64 + k1);
            float2 vA2 = *(const float2*)(W + rowA*64 + k2);
            float2 vB2 = *(const float2*)(W + (rowA+128)*64 + k2);
            u32 lo[4];
            splitpack2(vA1.x, vA1.y, Ahi[kk][0], lo[0]);
            splitpack2(vB1.x, vB1.y, Ahi[kk][1], lo[1]);
            splitpack2(vA2.x, vA2.y, Ahi[kk][2], lo[2]);
            splitpack2(vB2.x, vB2.y, Ahi[kk][3], lo[3]);
            *(uint4*)(alo_s + (kk*512 + tid)*4) = make_uint4(lo[0], lo[1], lo[2], lo[3]);
        }
        // ---- transition into buf0: rows 64+q = h1_T, rows q = r1(0); prefetch r1(1) ----
        {
            char* h0 = sm + OFF_H;
            u32 hA, lA, hB, lB;
            splitpack2(hl[0], hl[1], hA, lA);
            splitpack2(hl[2], hl[3], hB, lB);
            *(u32*)(h0 + (64+q)*PB + 2*bb0)       = hA;
            *(u32*)(h0 + (64+q)*PB + 2*bb0 + 16)  = hB;
            *(u32*)(h0 + (192+q)*PB + 2*bb0)      = lA;
            *(u32*)(h0 + (192+q)*PB + 2*bb0 + 16) = lB;
            size_t ri = (size_t)q*32 + bb0;
            *(u32*)(h0 + q*PB + 2*bb0)            = *(const u32*)(r1h + ri);
            *(u32*)(h0 + q*PB + 2*bb0 + 16)       = *(const u32*)(r1h + ri + 8);
            *(u32*)(h0 + (128+q)*PB + 2*bb0)      = *(const u32*)(r1l + ri);
            *(u32*)(h0 + (128+q)*PB + 2*bb0 + 16) = *(const u32*)(r1l + ri + 8);
            r1nh0 = *(const u32*)(r1h + 2048 + ri);
            r1nh1 = *(const u32*)(r1h + 2048 + ri + 8);
            r1nl0 = *(const u32*)(r1l + 2048 + ri);
            r1nl1 = *(const u32*)(r1l + 2048 + ri + 8);
        }
        __syncthreads();

        // ================= layer 2 =================
        for (int t = 0; t < TLEN; t++) {
            float cP[4][4], cQ[4][4];
            #pragma unroll
            for (int n = 0; n < 4; n++)
                #pragma unroll
                for (int j = 0; j < 4; j++) { cP[n][j] = 0.0f; cQ[n][j] = 0.0f; }
            do_mma<8>(hsm0 + (t&1)*HBUFB + laneoff, alo0, Ahi, cP, cQ);
            float c[4][4];
            #pragma unroll
            for (int n = 0; n < 4; n++)
                #pragma unroll
                for (int j = 0; j < 4; j++) c[n][j] = cP[n][j] + cQ[n][j];
            float rx[2][4];
            #pragma unroll
            for (int n2 = 0; n2 < 2; n2++)
                #pragma unroll
                for (int j = 0; j < 4; j++) {
                    float send = glo ? c[2+n2][j] : c[n2][j];
                    rx[n2][j] = __shfl_xor_sync(0xffffffffu, send, 16);
                }
            float hcur[4];
            #pragma unroll
            for (int j = 0; j < 4; j++) {
                int n2 = j >> 1, col = j & 1;
                float gi = (glo ? c[n2][col]    : rx[n2][col])    + b2f[0];
                float f  = (glo ? rx[n2][col]   : c[2+n2][col])   + b2f[1];
                float gg = (glo ? c[n2][2+col]  : rx[n2][2+col])  + b2f[2];
                float o  = (glo ? rx[n2][2+col] : c[2+n2][2+col]) + b2f[3];
                float cn = fmaf(sigf(f), cst[j], sigf(gi)*tanhf_(gg));
                cst[j] = cn;
                hcur[j] = sigf(o)*tanhf_(cn);
            }
            if (t + 1 < TLEN) {
                u32 hA, lA, hB, lB;
                splitpack2(hcur[0], hcur[1], hA, lA);
                splitpack2(hcur[2], hcur[3], hB, lB);
                char* hw = sm + OFF_H + ((t+1)&1)*HBUFB;
                *(u32*)(hw + (64+q)*PB + 2*bb0)       = hA;
                *(u32*)(hw + (64+q)*PB + 2*bb0 + 16)  = hB;
                *(u32*)(hw + (192+q)*PB + 2*bb0)      = lA;
                *(u32*)(hw + (192+q)*PB + 2*bb0 + 16) = lB;
                *(u32*)(hw + q*PB + 2*bb0)            = r1nh0;
                *(u32*)(hw + q*PB + 2*bb0 + 16)       = r1nh1;
                *(u32*)(hw + (128+q)*PB + 2*bb0)      = r1nl0;
                *(u32*)(hw + (128+q)*PB + 2*bb0 + 16) = r1nl1;
                if (t + 2 < TLEN) {
                    size_t ri = (size_t)(t+2)*2048 + q*32 + bb0;
                    r1nh0 = *(const u32*)(r1h + ri);
                    r1nh1 = *(const u32*)(r1h + ri + 8);
                    r1nl0 = *(const u32*)(r1l + ri);
                    r1nl1 = *(const u32*)(r1l + ri + 8);
                }
            } else {
                *(float2*)(scr + q*32 + bb0)     = make_float2(fmaxf(hcur[0],0.0f), fmaxf(hcur[1],0.0f));
                *(float2*)(scr + q*32 + bb0 + 8) = make_float2(fmaxf(hcur[2],0.0f), fmaxf(hcur[3],0.0f));
            }
            __syncthreads();
        }

        // ---- FC (collapsed) + window append ----
        if (tid < 32) {
            float s = *bcs + wcomb[64] * dsh[tid];
            #pragma unroll
            for (int uu = 0; uu < 64; uu++)
                s = fmaf(wcomb[uu], scr[uu*32 + tid], s);
            out[(size_t)(b0g + tid)*NSTEPS + step] = s;
            win[(TLEN + step)*32 + tid] = s;
        }
        __syncthreads();
    }
}

extern "C" void kernel_launch(void* const* d_in, const int* in_sizes, int n_in,
                              void* d_out, int out_size) {
    (void)in_sizes; (void)n_in; (void)out_size;
    const float* x    = (const float*)d_in[0];
    const float* Wih1 = (const float*)d_in[1];
    const float* Whh1 = (const float*)d_in[2];
    const float* bih1 = (const float*)d_in[3];
    const float* bhh1 = (const float*)d_in[4];
    const float* Wih2 = (const float*)d_in[5];
    const float* Whh2 = (const float*)d_in[6];
    const float* bih2 = (const float*)d_in[7];
    const float* bhh2 = (const float*)d_in[8];
    const float* fc1w = (const float*)d_in[9];
    const float* fc1b = (const float*)d_in[10];
    const float* fc2w = (const float*)d_in[11];
    const float* fc2b = (const float*)d_in[12];
    float* out = (float*)d_out;

    cudaFuncSetAttribute(lstm_rec_kernel, cudaFuncAttributeMaxDynamicSharedMemorySize, SMEM_BYTES);
    lstm_rec_kernel<<<GRID, NTHR, SMEM_BYTES>>>(x, Wih1, Whh1, bih1, bhh1,
                                                Wih2, Whh2, bih2, bhh2,
                                                fc1w, fc1b, fc2w, fc2b, out);
}